// round 1
// baseline (speedup 1.0000x reference)
#include <cuda_runtime.h>
#include <math.h>

// Problem constants
#define BB 2
#define NN 2048
#define DD 512
#define HH 8
#define HDIM 64
#define LL 2
#define TOK (BB*NN)          // 4096 rows

// Scratch (device globals — no allocation allowed)
__device__ float g_h  [(size_t)TOK * DD];          // residual stream
__device__ float g_x  [(size_t)TOK * DD];          // LN output
__device__ float g_qkv[(size_t)TOK * 3 * DD];      // qkv
__device__ float g_sc [(size_t)BB * HH * NN * NN]; // attention scores (268MB)
__device__ float g_ao [(size_t)TOK * DD];          // attention output (pre out-proj)
__device__ float g_fc [(size_t)TOK * 4 * DD];      // MLP hidden

// ---------------------------------------------------------------------------
// pos add: h = emb + pos (broadcast over batch)
// ---------------------------------------------------------------------------
__global__ void addpos_k(const float* __restrict__ e, const float* __restrict__ p,
                         float* __restrict__ h)
{
    long long i = (long long)blockIdx.x * 256 + threadIdx.x;
    long long nd = i % ((long long)NN * DD);
    h[i] = e[i] + p[nd];
}

// ---------------------------------------------------------------------------
// LayerNorm: one block (128 threads) per row of 512
// ---------------------------------------------------------------------------
__global__ void layernorm_k(const float* __restrict__ x, const float* __restrict__ g,
                            const float* __restrict__ b, float* __restrict__ y)
{
    int row = blockIdx.x;
    int t = threadIdx.x;                 // 0..127
    const float* xr = x + (long long)row * DD;
    float4 v = *(const float4*)(xr + t * 4);
    float s  = v.x + v.y + v.z + v.w;
    float ss = v.x*v.x + v.y*v.y + v.z*v.z + v.w*v.w;

    // reduce across 4 warps
    #pragma unroll
    for (int o = 16; o; o >>= 1) {
        s  += __shfl_xor_sync(0xffffffffu, s,  o);
        ss += __shfl_xor_sync(0xffffffffu, ss, o);
    }
    __shared__ float r1[4], r2[4];
    int wid = t >> 5, lane = t & 31;
    if (lane == 0) { r1[wid] = s; r2[wid] = ss; }
    __syncthreads();
    float sum   = r1[0] + r1[1] + r1[2] + r1[3];
    float sumsq = r2[0] + r2[1] + r2[2] + r2[3];

    float mu   = sum * (1.0f / DD);
    float var  = sumsq * (1.0f / DD) - mu * mu;
    float rstd = rsqrtf(var + 1e-5f);

    float4 gg = *(const float4*)(g + t * 4);
    float4 bb = *(const float4*)(b + t * 4);
    float4 o;
    o.x = (v.x - mu) * rstd * gg.x + bb.x;
    o.y = (v.y - mu) * rstd * gg.y + bb.y;
    o.z = (v.z - mu) * rstd * gg.z + bb.z;
    o.w = (v.w - mu) * rstd * gg.w + bb.w;
    *(float4*)(y + (long long)row * DD + t * 4) = o;
}

// ---------------------------------------------------------------------------
// Row softmax with exclude-self mask; row length NN, 256 threads x 8 elems
// ---------------------------------------------------------------------------
__global__ void softmax_k(float* __restrict__ s)
{
    int q  = blockIdx.x;
    int bh = blockIdx.y;
    float* row = s + ((long long)bh * NN + q) * (long long)NN;
    int t = threadIdx.x;

    float v[8];
    #pragma unroll
    for (int i = 0; i < 8; i++) {
        int c = t + i * 256;
        float x = row[c];
        v[i] = (c == q) ? -1e30f : x;
    }
    float m = v[0];
    #pragma unroll
    for (int i = 1; i < 8; i++) m = fmaxf(m, v[i]);

    __shared__ float red[8];
    #pragma unroll
    for (int o = 16; o; o >>= 1) m = fmaxf(m, __shfl_xor_sync(0xffffffffu, m, o));
    int wid = t >> 5, lane = t & 31;
    if (lane == 0) red[wid] = m;
    __syncthreads();
    float mall = red[0];
    #pragma unroll
    for (int i = 1; i < 8; i++) mall = fmaxf(mall, red[i]);
    __syncthreads();

    float sum = 0.f;
    #pragma unroll
    for (int i = 0; i < 8; i++) { v[i] = __expf(v[i] - mall); sum += v[i]; }
    #pragma unroll
    for (int o = 16; o; o >>= 1) sum += __shfl_xor_sync(0xffffffffu, sum, o);
    if (lane == 0) red[wid] = sum;
    __syncthreads();
    float tot = 0.f;
    #pragma unroll
    for (int i = 0; i < 8; i++) tot += red[i];
    float inv = 1.0f / tot;
    #pragma unroll
    for (int i = 0; i < 8; i++) row[t + i * 256] = v[i] * inv;
}

// ---------------------------------------------------------------------------
// Generic tiled GEMM: C = alpha*(A@B) + bias + res, optional GELU, opt B^T,
// batched over blockIdx.z with (b,h)-decomposed offsets.
// Tile 64x64, K-step 16, 256 threads, 4x4 micro-tile.
// All problem dims here are multiples of 64 (M,N) and 16 (K): no bounds checks.
// ---------------------------------------------------------------------------
__device__ __forceinline__ float gelu_new(float x)
{
    float x3 = x * x * x;
    return 0.5f * x * (1.0f + tanhf(0.7978845608028654f * (x + 0.044715f * x3)));
}

__global__ void __launch_bounds__(256)
gemm64(const float* __restrict__ A, const float* __restrict__ B,
       const float* __restrict__ bias, const float* res, float* C,
       int M, int N, int K, int lda, int ldb, int ldc,
       long long sAb, long long sAh, long long sBb, long long sBh,
       long long sCb, long long sCh,
       float alpha, int transB, int act)
{
    int z  = blockIdx.z;
    int zb = z / HH, zh = z % HH;
    A += (long long)zb * sAb + (long long)zh * sAh;
    B += (long long)zb * sBb + (long long)zh * sBh;
    C += (long long)zb * sCb + (long long)zh * sCh;
    if (res) res += (long long)zb * sCb + (long long)zh * sCh;

    __shared__ float As[16][64];
    __shared__ float Bs[16][64];

    int t  = threadIdx.x;
    int m0 = blockIdx.y * 64;
    int n0 = blockIdx.x * 64;
    int tx = t & 15, ty = t >> 4;

    float acc[4][4] = {};

    for (int k0 = 0; k0 < K; k0 += 16) {
        {   // A tile: 64 rows x 16 k, float4 per thread
            int r  = t >> 2;
            int kk = (t & 3) * 4;
            float4 v = *(const float4*)(A + (long long)(m0 + r) * lda + k0 + kk);
            As[kk + 0][r] = v.x; As[kk + 1][r] = v.y;
            As[kk + 2][r] = v.z; As[kk + 3][r] = v.w;
        }
        if (!transB) {   // B[k][n]
            int kk = t >> 4;
            int nn = (t & 15) * 4;
            float4 v = *(const float4*)(B + (long long)(k0 + kk) * ldb + n0 + nn);
            *(float4*)&Bs[kk][nn] = v;
        } else {         // B logical [K,N] = Bm[n*ldb + k]
            int nn = t >> 2;
            int kk = (t & 3) * 4;
            float4 v = *(const float4*)(B + (long long)(n0 + nn) * ldb + k0 + kk);
            Bs[kk + 0][nn] = v.x; Bs[kk + 1][nn] = v.y;
            Bs[kk + 2][nn] = v.z; Bs[kk + 3][nn] = v.w;
        }
        __syncthreads();
        #pragma unroll
        for (int kk = 0; kk < 16; kk++) {
            float4 a4 = *(const float4*)&As[kk][ty * 4];
            float4 b4 = *(const float4*)&Bs[kk][tx * 4];
            float av[4] = {a4.x, a4.y, a4.z, a4.w};
            float bv[4] = {b4.x, b4.y, b4.z, b4.w};
            #pragma unroll
            for (int i = 0; i < 4; i++)
                #pragma unroll
                for (int j = 0; j < 4; j++)
                    acc[i][j] += av[i] * bv[j];
        }
        __syncthreads();
    }

    #pragma unroll
    for (int i = 0; i < 4; i++) {
        int row = m0 + ty * 4 + i;
        #pragma unroll
        for (int j = 0; j < 4; j++) {
            int col = n0 + tx * 4 + j;
            float v = acc[i][j] * alpha;
            if (bias) v += bias[col];
            if (act)  v = gelu_new(v);
            if (res)  v += res[(long long)row * ldc + col];
            C[(long long)row * ldc + col] = v;
        }
    }
}

// ---------------------------------------------------------------------------
extern "C" void kernel_launch(void* const* d_in, const int* in_sizes, int n_in,
                              void* d_out, int out_size)
{
    const float* emb      = (const float*)d_in[0];
    const float* pos      = (const float*)d_in[1];
    const float* c_attn_w = (const float*)d_in[2];
    const float* c_attn_b = (const float*)d_in[3];
    const float* out_w    = (const float*)d_in[4];
    const float* out_b    = (const float*)d_in[5];
    const float* ln1_g    = (const float*)d_in[6];
    const float* ln1_b    = (const float*)d_in[7];
    const float* c_fc_w   = (const float*)d_in[8];
    const float* c_fc_b   = (const float*)d_in[9];
    const float* c_proj_w = (const float*)d_in[10];
    const float* c_proj_b = (const float*)d_in[11];
    const float* ln2_g    = (const float*)d_in[12];
    const float* ln2_b    = (const float*)d_in[13];

    float *h_, *x_, *qkv_, *sc_, *ao_, *fc_;
    cudaGetSymbolAddress((void**)&h_,   g_h);
    cudaGetSymbolAddress((void**)&x_,   g_x);
    cudaGetSymbolAddress((void**)&qkv_, g_qkv);
    cudaGetSymbolAddress((void**)&sc_,  g_sc);
    cudaGetSymbolAddress((void**)&ao_,  g_ao);
    cudaGetSymbolAddress((void**)&fc_,  g_fc);

    const long long ZERO = 0;
    (void)ZERO; (void)in_sizes; (void)n_in; (void)out_size;

    // h = emb + pos
    addpos_k<<<(TOK * DD) / 256, 256>>>(emb, pos, h_);

    for (int l = 0; l < LL; l++) {
        const float* aw  = c_attn_w + (long long)l * DD * 3 * DD;
        const float* ab  = c_attn_b + (long long)l * 3 * DD;
        const float* ow  = out_w    + (long long)l * DD * DD;
        const float* ob  = out_b    + (long long)l * DD;
        const float* fw  = c_fc_w   + (long long)l * DD * 4 * DD;
        const float* fb  = c_fc_b   + (long long)l * 4 * DD;
        const float* pw  = c_proj_w + (long long)l * 4 * DD * DD;
        const float* pb  = c_proj_b + (long long)l * DD;

        // x = LN1(h)
        layernorm_k<<<TOK, 128>>>(h_, ln1_g + l * DD, ln1_b + l * DD, x_);

        // qkv = x @ c_attn_w + b          [4096,1536] K=512
        gemm64<<<dim3(3 * DD / 64, TOK / 64, 1), 256>>>(
            x_, aw, ab, nullptr, qkv_,
            TOK, 3 * DD, DD, DD, 3 * DD, 3 * DD,
            0, 0, 0, 0, 0, 0, 1.0f, 0, 0);

        // S = 0.125 * Q @ K^T  (batched over b*h)  [2048,2048] K=64
        gemm64<<<dim3(NN / 64, NN / 64, BB * HH), 256>>>(
            qkv_, qkv_ + DD, nullptr, nullptr, sc_,
            NN, NN, HDIM, 3 * DD, 3 * DD, NN,
            (long long)NN * 3 * DD, HDIM,
            (long long)NN * 3 * DD, HDIM,
            (long long)HH * NN * NN, (long long)NN * NN,
            0.125f, 1, 0);

        // softmax rows w/ self-mask
        softmax_k<<<dim3(NN, BB * HH), 256>>>(sc_);

        // O = P @ V  (batched)  [2048,64] K=2048 -> write heads-merged into ao
        gemm64<<<dim3(1, NN / 64, BB * HH), 256>>>(
            sc_, qkv_ + 2 * DD, nullptr, nullptr, ao_,
            NN, HDIM, NN, NN, 3 * DD, DD,
            (long long)HH * NN * NN, (long long)NN * NN,
            (long long)NN * 3 * DD, HDIM,
            (long long)NN * DD, HDIM,
            1.0f, 0, 0);

        // h = ao @ out_w + out_b + h     [4096,512] K=512
        gemm64<<<dim3(DD / 64, TOK / 64, 1), 256>>>(
            ao_, ow, ob, h_, h_,
            TOK, DD, DD, DD, DD, DD,
            0, 0, 0, 0, 0, 0, 1.0f, 0, 0);

        // x = LN2(h)
        layernorm_k<<<TOK, 128>>>(h_, ln2_g + l * DD, ln2_b + l * DD, x_);

        // fc = gelu(x @ c_fc_w + b)      [4096,2048] K=512
        gemm64<<<dim3(4 * DD / 64, TOK / 64, 1), 256>>>(
            x_, fw, fb, nullptr, fc_,
            TOK, 4 * DD, DD, DD, 4 * DD, 4 * DD,
            0, 0, 0, 0, 0, 0, 1.0f, 0, 1);

        // h = fc @ c_proj_w + b + h      [4096,512] K=2048  (last layer -> d_out)
        float* dst = (l == LL - 1) ? (float*)d_out : h_;
        gemm64<<<dim3(DD / 64, TOK / 64, 1), 256>>>(
            fc_, pw, pb, h_, dst,
            TOK, DD, 4 * DD, 4 * DD, DD, DD,
            0, 0, 0, 0, 0, 0, 1.0f, 0, 0);
    }
}

// round 3
// speedup vs baseline: 2.8333x; 2.8333x over previous
#include <cuda_runtime.h>
#include <cstdint>
#include <math.h>

// Problem constants
#define BB 2
#define NN 2048
#define DD 512
#define HH 8
#define HDIM 64
#define LL 2
#define TOK (BB*NN)          // 4096 rows

// Scratch (device globals — no allocation allowed)
__device__ float g_h  [(size_t)TOK * DD];
__device__ float g_x  [(size_t)TOK * DD];
__device__ float g_qkv[(size_t)TOK * 3 * DD];
__device__ float g_sc [(size_t)BB * HH * NN * NN];   // 268MB scores
__device__ float g_ao [(size_t)TOK * DD];
__device__ float g_fc [(size_t)TOK * 4 * DD];
__device__ float g_wt [3145728];                      // transposed weights (one layer)
__device__ float g_vt [(size_t)BB * HH * HDIM * NN];  // V transposed [b*h][hd][n]

#define AW_T 0          // [1536,512]
#define OW_T 786432     // [512,512]
#define FW_T 1048576    // [2048,512]
#define PW_T 2097152    // [512,2048]

// ---------------------------------------------------------------------------
__device__ __forceinline__ uint32_t smem_u32(const void* p) {
    uint32_t a;
    asm("{ .reg .u64 t; cvta.to.shared.u64 t, %1; cvt.u32.u64 %0, t; }" : "=r"(a) : "l"(p));
    return a;
}
__device__ __forceinline__ uint32_t f2tf(float x) {
    uint32_t u;
    asm("cvt.rna.tf32.f32 %0, %1;" : "=r"(u) : "f"(x));
    return u;
}
__device__ __forceinline__ void ldsm4(uint32_t& r0, uint32_t& r1, uint32_t& r2, uint32_t& r3,
                                      uint32_t addr) {
    asm volatile("ldmatrix.sync.aligned.m8n8.x4.shared.b16 {%0,%1,%2,%3}, [%4];"
                 : "=r"(r0), "=r"(r1), "=r"(r2), "=r"(r3) : "r"(addr));
}
__device__ __forceinline__ void mma8(float* d, const uint32_t* a, const uint32_t* b) {
    asm volatile(
        "mma.sync.aligned.m16n8k8.row.col.f32.tf32.tf32.f32 "
        "{%0,%1,%2,%3}, {%4,%5,%6,%7}, {%8,%9}, {%0,%1,%2,%3};"
        : "+f"(d[0]), "+f"(d[1]), "+f"(d[2]), "+f"(d[3])
        : "r"(a[0]), "r"(a[1]), "r"(a[2]), "r"(a[3]), "r"(b[0]), "r"(b[1]));
}
__device__ __forceinline__ float gelu_new(float x) {
    float x3 = x * x * x;
    return 0.5f * x * (1.0f + tanhf(0.7978845608028654f * (x + 0.044715f * x3)));
}

// ---------------------------------------------------------------------------
// tf32 tensor-core GEMM: C[M,N] = alpha*(A @ B^T) + bias (+GELU) (+res)
// A: [M,K] K-major (lda).  B: [N,K] K-major (ldb).  CTA tile 128 x CTA_N.
// BK=32 (128B rows, SW128 swizzle). 256 threads = 8 warps (2m x 4n).
// K % 32 == 0, M % 128 == 0, N % CTA_N == 0. Batched via blockIdx.z.
// ---------------------------------------------------------------------------
template<int CTA_N>
__global__ void __launch_bounds__(256)
mgemm(const float* __restrict__ A, const float* __restrict__ B,
      const float* __restrict__ bias, const float* res, float* __restrict__ C,
      int K, int lda, int ldb, int ldc,
      long long sAb, long long sAh, long long sBb, long long sBh,
      long long sCb, long long sCh, float alpha, int act)
{
    constexpr int WN  = CTA_N / 4;       // warp n-tile (32 or 16)
    constexpr int NB  = WN / 8;          // n8 tiles per warp (4 or 2)
    constexpr int NP  = WN / 16;         // ldmatrix B pairs (2 or 1)
    constexpr int BL  = CTA_N / 32;      // B float4 loads per thread (4 or 2)
    constexpr int ABYT   = 128 * 128;        // A tile bytes
    constexpr int STAGEB = ABYT + CTA_N * 128;

    extern __shared__ char smem[];
    uint32_t sbase = smem_u32(smem);

    int z = blockIdx.z, zb = z / HH, zh = z % HH;
    A += (long long)zb * sAb + (long long)zh * sAh;
    B += (long long)zb * sBb + (long long)zh * sBh;
    C += (long long)zb * sCb + (long long)zh * sCh;
    if (res) res += (long long)zb * sCb + (long long)zh * sCh;

    const int t = threadIdx.x;
    const int lane = t & 31;
    const int w = t >> 5, wm = w >> 2, wn = w & 3;
    const int m0 = blockIdx.y * 128;
    const int n0 = blockIdx.x * CTA_N;

    float acc[4][NB][4];
    #pragma unroll
    for (int i = 0; i < 4; i++)
        #pragma unroll
        for (int j = 0; j < NB; j++)
            #pragma unroll
            for (int q = 0; q < 4; q++) acc[i][j][q] = 0.f;

    const int KT = K / 32;
    float4 ra[4], rb[BL];

    // thread -> (row, k-quad) for loads
    const int lrA[4] = { (t + 0) >> 3, (t + 256) >> 3, (t + 512) >> 3, (t + 768) >> 3 };
    const int lkq = t & 7;

    auto load_regs = [&](int kt) {
        const float* Ak = A + kt * 32 + lkq * 4;
        #pragma unroll
        for (int i = 0; i < 4; i++)
            ra[i] = *(const float4*)(Ak + (long long)(m0 + lrA[i]) * lda);
        const float* Bk = B + kt * 32 + lkq * 4;
        #pragma unroll
        for (int i = 0; i < BL; i++)
            rb[i] = *(const float4*)(Bk + (long long)(n0 + ((t + i * 256) >> 3)) * ldb);
    };
    auto store_smem = [&](int st) {
        char* sA = smem + st * STAGEB;
        char* sB = sA + ABYT;
        #pragma unroll
        for (int i = 0; i < 4; i++) {
            int r = lrA[i];
            uint4 u = { f2tf(ra[i].x), f2tf(ra[i].y), f2tf(ra[i].z), f2tf(ra[i].w) };
            *(uint4*)(sA + r * 128 + ((lkq ^ (r & 7)) << 4)) = u;
        }
        #pragma unroll
        for (int i = 0; i < BL; i++) {
            int r = (t + i * 256) >> 3;
            uint4 u = { f2tf(rb[i].x), f2tf(rb[i].y), f2tf(rb[i].z), f2tf(rb[i].w) };
            *(uint4*)(sB + r * 128 + ((lkq ^ (r & 7)) << 4)) = u;
        }
    };

    load_regs(0);
    store_smem(0);
    __syncthreads();

    const int arow0 = wm * 64 + (lane & 7) + ((lane >> 3) & 1) * 8;
    const int ach0  = lane >> 4;
    const int brow0 = wn * WN + ((lane >> 4) & 1) * 8 + (lane & 7);
    const int bch0  = (lane >> 3) & 1;

    for (int kt = 0; kt < KT; kt++) {
        if (kt + 1 < KT) load_regs(kt + 1);

        uint32_t sA = sbase + (kt & 1) * STAGEB;
        uint32_t sB = sA + ABYT;
        #pragma unroll
        for (int ks = 0; ks < 4; ks++) {
            uint32_t a[4][4];
            #pragma unroll
            for (int mi = 0; mi < 4; mi++) {
                int r = arow0 + mi * 16;
                uint32_t ad = sA + r * 128 + (((ks * 2 + ach0) ^ (r & 7)) << 4);
                ldsm4(a[mi][0], a[mi][1], a[mi][2], a[mi][3], ad);
            }
            uint32_t b[NP][4];
            #pragma unroll
            for (int pi = 0; pi < NP; pi++) {
                int r = brow0 + pi * 16;
                uint32_t bd = sB + r * 128 + (((ks * 2 + bch0) ^ (r & 7)) << 4);
                ldsm4(b[pi][0], b[pi][1], b[pi][2], b[pi][3], bd);
            }
            #pragma unroll
            for (int mi = 0; mi < 4; mi++)
                #pragma unroll
                for (int ni = 0; ni < NB; ni++)
                    mma8(acc[mi][ni], a[mi], &b[ni >> 1][(ni & 1) * 2]);
        }

        if (kt + 1 < KT) store_smem((kt + 1) & 1);
        __syncthreads();
    }

    // Epilogue: fragment rows groupID / groupID+8; cols (lane&3)*2, +1
    const int gid = lane >> 2;
    #pragma unroll
    for (int mi = 0; mi < 4; mi++) {
        #pragma unroll
        for (int ni = 0; ni < NB; ni++) {
            int r  = m0 + wm * 64 + mi * 16 + gid;
            int c  = n0 + wn * WN + ni * 8 + (lane & 3) * 2;
            float2 bv = bias ? *(const float2*)(bias + c) : make_float2(0.f, 0.f);
            #pragma unroll
            for (int half = 0; half < 2; half++) {
                int row = r + half * 8;
                float v0 = acc[mi][ni][half * 2 + 0] * alpha + bv.x;
                float v1 = acc[mi][ni][half * 2 + 1] * alpha + bv.y;
                if (act) { v0 = gelu_new(v0); v1 = gelu_new(v1); }
                if (res) {
                    float2 rv = *(const float2*)(res + (long long)row * ldc + c);
                    v0 += rv.x; v1 += rv.y;
                }
                float2 o; o.x = v0; o.y = v1;
                *(float2*)(C + (long long)row * ldc + c) = o;
            }
        }
    }
}

// ---------------------------------------------------------------------------
__global__ void transpose_k(const float* __restrict__ src, float* __restrict__ dst,
                            int lds, int ldd,
                            long long szb, long long szh, long long dzb, long long dzh)
{
    __shared__ float tile[32][33];
    int z = blockIdx.z, zb = z / HH, zh = z % HH;
    src += (long long)zb * szb + (long long)zh * szh;
    dst += (long long)zb * dzb + (long long)zh * dzh;
    int c0 = blockIdx.x * 32, r0 = blockIdx.y * 32;
    int tx = threadIdx.x, ty = threadIdx.y;   // 32 x 8
    #pragma unroll
    for (int i = 0; i < 32; i += 8)
        tile[ty + i][tx] = src[(long long)(r0 + ty + i) * lds + c0 + tx];
    __syncthreads();
    #pragma unroll
    for (int i = 0; i < 32; i += 8)
        dst[(long long)(c0 + ty + i) * ldd + r0 + tx] = tile[tx][ty + i];
}

__global__ void addpos_k(const float* __restrict__ e, const float* __restrict__ p,
                         float* __restrict__ h)
{
    long long i = (long long)blockIdx.x * 256 + threadIdx.x;
    long long nd = i % ((long long)NN * DD);
    h[i] = e[i] + p[nd];
}

__global__ void layernorm_k(const float* __restrict__ x, const float* __restrict__ g,
                            const float* __restrict__ b, float* __restrict__ y)
{
    int row = blockIdx.x;
    int t = threadIdx.x;
    const float* xr = x + (long long)row * DD;
    float4 v = *(const float4*)(xr + t * 4);
    float s  = v.x + v.y + v.z + v.w;
    float ss = v.x*v.x + v.y*v.y + v.z*v.z + v.w*v.w;
    #pragma unroll
    for (int o = 16; o; o >>= 1) {
        s  += __shfl_xor_sync(0xffffffffu, s,  o);
        ss += __shfl_xor_sync(0xffffffffu, ss, o);
    }
    __shared__ float r1[4], r2[4];
    int wid = t >> 5, lane = t & 31;
    if (lane == 0) { r1[wid] = s; r2[wid] = ss; }
    __syncthreads();
    float sum   = r1[0] + r1[1] + r1[2] + r1[3];
    float sumsq = r2[0] + r2[1] + r2[2] + r2[3];
    float mu   = sum * (1.0f / DD);
    float var  = sumsq * (1.0f / DD) - mu * mu;
    float rstd = rsqrtf(var + 1e-5f);
    float4 gg = *(const float4*)(g + t * 4);
    float4 bb = *(const float4*)(b + t * 4);
    float4 o;
    o.x = (v.x - mu) * rstd * gg.x + bb.x;
    o.y = (v.y - mu) * rstd * gg.y + bb.y;
    o.z = (v.z - mu) * rstd * gg.z + bb.z;
    o.w = (v.w - mu) * rstd * gg.w + bb.w;
    *(float4*)(y + (long long)row * DD + t * 4) = o;
}

__global__ void softmax_k(float* __restrict__ s)
{
    int q  = blockIdx.x;
    int bh = blockIdx.y;
    float* row = s + ((long long)bh * NN + q) * (long long)NN;
    int t = threadIdx.x;
    float v[8];
    #pragma unroll
    for (int i = 0; i < 8; i++) {
        int c = t + i * 256;
        float x = row[c];
        v[i] = (c == q) ? -1e30f : x;
    }
    float m = v[0];
    #pragma unroll
    for (int i = 1; i < 8; i++) m = fmaxf(m, v[i]);
    __shared__ float red[8];
    #pragma unroll
    for (int o = 16; o; o >>= 1) m = fmaxf(m, __shfl_xor_sync(0xffffffffu, m, o));
    int wid = t >> 5, lane = t & 31;
    if (lane == 0) red[wid] = m;
    __syncthreads();
    float mall = red[0];
    #pragma unroll
    for (int i = 1; i < 8; i++) mall = fmaxf(mall, red[i]);
    __syncthreads();
    float sum = 0.f;
    #pragma unroll
    for (int i = 0; i < 8; i++) { v[i] = __expf(v[i] - mall); sum += v[i]; }
    #pragma unroll
    for (int o = 16; o; o >>= 1) sum += __shfl_xor_sync(0xffffffffu, sum, o);
    if (lane == 0) red[wid] = sum;
    __syncthreads();
    float tot = 0.f;
    #pragma unroll
    for (int i = 0; i < 8; i++) tot += red[i];
    float inv = 1.0f / tot;
    #pragma unroll
    for (int i = 0; i < 8; i++) row[t + i * 256] = v[i] * inv;
}

// ---------------------------------------------------------------------------
extern "C" void kernel_launch(void* const* d_in, const int* in_sizes, int n_in,
                              void* d_out, int out_size)
{
    const float* emb      = (const float*)d_in[0];
    const float* pos      = (const float*)d_in[1];
    const float* c_attn_w = (const float*)d_in[2];
    const float* c_attn_b = (const float*)d_in[3];
    const float* out_w    = (const float*)d_in[4];
    const float* out_b    = (const float*)d_in[5];
    const float* ln1_g    = (const float*)d_in[6];
    const float* ln1_b    = (const float*)d_in[7];
    const float* c_fc_w   = (const float*)d_in[8];
    const float* c_fc_b   = (const float*)d_in[9];
    const float* c_proj_w = (const float*)d_in[10];
    const float* c_proj_b = (const float*)d_in[11];
    const float* ln2_g    = (const float*)d_in[12];
    const float* ln2_b    = (const float*)d_in[13];
    (void)in_sizes; (void)n_in; (void)out_size;

    float *h_, *x_, *qkv_, *sc_, *ao_, *fc_, *wt_, *vt_;
    cudaGetSymbolAddress((void**)&h_,   g_h);
    cudaGetSymbolAddress((void**)&x_,   g_x);
    cudaGetSymbolAddress((void**)&qkv_, g_qkv);
    cudaGetSymbolAddress((void**)&sc_,  g_sc);
    cudaGetSymbolAddress((void**)&ao_,  g_ao);
    cudaGetSymbolAddress((void**)&fc_,  g_fc);
    cudaGetSymbolAddress((void**)&wt_,  g_wt);
    cudaGetSymbolAddress((void**)&vt_,  g_vt);

    const int SM128 = 2 * (128 + 128) * 128;   // 65536
    const int SM64  = 2 * (128 + 64)  * 128;   // 49152
    cudaFuncSetAttribute(mgemm<128>, cudaFuncAttributeMaxDynamicSharedMemorySize, SM128);
    cudaFuncSetAttribute(mgemm<64>,  cudaFuncAttributeMaxDynamicSharedMemorySize, SM64);

    dim3 tb(32, 8);

    addpos_k<<<(TOK * DD) / 256, 256>>>(emb, pos, h_);

    for (int l = 0; l < LL; l++) {
        const float* aw = c_attn_w + (long long)l * DD * 3 * DD;
        const float* ab = c_attn_b + (long long)l * 3 * DD;
        const float* ow = out_w    + (long long)l * DD * DD;
        const float* ob = out_b    + (long long)l * DD;
        const float* fw = c_fc_w   + (long long)l * DD * 4 * DD;
        const float* fb = c_fc_b   + (long long)l * 4 * DD;
        const float* pw = c_proj_w + (long long)l * 4 * DD * DD;
        const float* pb = c_proj_b + (long long)l * DD;

        // Weight transposes -> K-major B operands
        transpose_k<<<dim3(3*DD/32, DD/32, 1), tb>>>(aw, wt_ + AW_T, 3*DD, DD, 0,0,0,0);
        transpose_k<<<dim3(DD/32,   DD/32, 1), tb>>>(ow, wt_ + OW_T, DD,   DD, 0,0,0,0);
        transpose_k<<<dim3(4*DD/32, DD/32, 1), tb>>>(fw, wt_ + FW_T, 4*DD, DD, 0,0,0,0);
        transpose_k<<<dim3(DD/32, 4*DD/32, 1), tb>>>(pw, wt_ + PW_T, DD, 4*DD, 0,0,0,0);

        // x = LN1(h)
        layernorm_k<<<TOK, 128>>>(h_, ln1_g + l * DD, ln1_b + l * DD, x_);

        // qkv = x @ c_attn_w + b     [4096,1536] K=512
        mgemm<128><<<dim3(3*DD/128, TOK/128, 1), 256, SM128>>>(
            x_, wt_ + AW_T, ab, nullptr, qkv_,
            DD, DD, DD, 3*DD, 0,0,0,0,0,0, 1.0f, 0);

        // S = 0.125 * Q @ K^T  batched  [2048,2048] K=64
        mgemm<128><<<dim3(NN/128, NN/128, BB*HH), 256, SM128>>>(
            qkv_, qkv_ + DD, nullptr, nullptr, sc_,
            HDIM, 3*DD, 3*DD, NN,
            (long long)NN*3*DD, HDIM,
            (long long)NN*3*DD, HDIM,
            (long long)HH*NN*NN, (long long)NN*NN,
            0.125f, 0);

        // softmax with self-mask
        softmax_k<<<dim3(NN, BB*HH), 256>>>(sc_);

        // vt[b*h][hd][n] = V^T
        transpose_k<<<dim3(HDIM/32, NN/32, BB*HH), tb>>>(
            qkv_ + 2*DD, vt_, 3*DD, NN,
            (long long)NN*3*DD, HDIM,
            (long long)HH*HDIM*NN, (long long)HDIM*NN);

        // O = P @ V  batched  [2048,64] K=2048
        mgemm<64><<<dim3(HDIM/64, NN/128, BB*HH), 256, SM64>>>(
            sc_, vt_, nullptr, nullptr, ao_,
            NN, NN, NN, DD,
            (long long)HH*NN*NN, (long long)NN*NN,
            (long long)HH*HDIM*NN, (long long)HDIM*NN,
            (long long)NN*DD, HDIM,
            1.0f, 0);

        // h = ao @ out_w + out_b + h   [4096,512] K=512
        mgemm<128><<<dim3(DD/128, TOK/128, 1), 256, SM128>>>(
            ao_, wt_ + OW_T, ob, h_, h_,
            DD, DD, DD, DD, 0,0,0,0,0,0, 1.0f, 0);

        // x = LN2(h)
        layernorm_k<<<TOK, 128>>>(h_, ln2_g + l * DD, ln2_b + l * DD, x_);

        // fc = gelu(x @ c_fc_w + b)  [4096,2048] K=512
        mgemm<128><<<dim3(4*DD/128, TOK/128, 1), 256, SM128>>>(
            x_, wt_ + FW_T, fb, nullptr, fc_,
            DD, DD, DD, 4*DD, 0,0,0,0,0,0, 1.0f, 1);

        // h = fc @ c_proj_w + b + h  [4096,512] K=2048
        float* dst = (l == LL - 1) ? (float*)d_out : h_;
        mgemm<128><<<dim3(DD/128, TOK/128, 1), 256, SM128>>>(
            fc_, wt_ + PW_T, pb, h_, dst,
            4*DD, 4*DD, 4*DD, DD, 0,0,0,0,0,0, 1.0f, 0);
    }
}

// round 4
// speedup vs baseline: 3.4963x; 1.2340x over previous
#include <cuda_runtime.h>
#include <cstdint>
#include <math.h>

// Problem constants
#define BB 2
#define NN 2048
#define DD 512
#define HH 8
#define HDIM 64
#define LL 2
#define TOK (BB*NN)          // 4096 rows

// Scratch (device globals — no allocation allowed)
__device__ float g_h  [(size_t)TOK * DD];
__device__ float g_x  [(size_t)TOK * DD];
__device__ float g_qkv[(size_t)TOK * 3 * DD];
__device__ float g_ao [(size_t)TOK * DD];
__device__ float g_fc [(size_t)TOK * 4 * DD];
__device__ float g_wt [3145728];                      // transposed weights (one layer)
__device__ float g_vt [(size_t)BB * HH * HDIM * NN];  // V transposed [b*h][hd][n]

#define AW_T 0          // [1536,512]
#define OW_T 786432     // [512,512]
#define FW_T 1048576    // [2048,512]
#define PW_T 2097152    // [512,2048]

// ---------------------------------------------------------------------------
__device__ __forceinline__ uint32_t smem_u32(const void* p) {
    uint32_t a;
    asm("{ .reg .u64 t; cvta.to.shared.u64 t, %1; cvt.u32.u64 %0, t; }" : "=r"(a) : "l"(p));
    return a;
}
__device__ __forceinline__ uint32_t f2tf(float x) {
    uint32_t u;
    asm("cvt.rna.tf32.f32 %0, %1;" : "=r"(u) : "f"(x));
    return u;
}
__device__ __forceinline__ void ldsm4(uint32_t& r0, uint32_t& r1, uint32_t& r2, uint32_t& r3,
                                      uint32_t addr) {
    asm volatile("ldmatrix.sync.aligned.m8n8.x4.shared.b16 {%0,%1,%2,%3}, [%4];"
                 : "=r"(r0), "=r"(r1), "=r"(r2), "=r"(r3) : "r"(addr));
}
__device__ __forceinline__ void mma8(float* d, const uint32_t* a, const uint32_t* b) {
    asm volatile(
        "mma.sync.aligned.m16n8k8.row.col.f32.tf32.tf32.f32 "
        "{%0,%1,%2,%3}, {%4,%5,%6,%7}, {%8,%9}, {%0,%1,%2,%3};"
        : "+f"(d[0]), "+f"(d[1]), "+f"(d[2]), "+f"(d[3])
        : "r"(a[0]), "r"(a[1]), "r"(a[2]), "r"(a[3]), "r"(b[0]), "r"(b[1]));
}
__device__ __forceinline__ float gelu_new(float x) {
    float x3 = x * x * x;
    return 0.5f * x * (1.0f + tanhf(0.7978845608028654f * (x + 0.044715f * x3)));
}

// ---------------------------------------------------------------------------
// tf32 tensor-core GEMM (unchanged from round 3, proven correct)
// ---------------------------------------------------------------------------
template<int CTA_N>
__global__ void __launch_bounds__(256)
mgemm(const float* __restrict__ A, const float* __restrict__ B,
      const float* __restrict__ bias, const float* res, float* __restrict__ C,
      int K, int lda, int ldb, int ldc,
      long long sAb, long long sAh, long long sBb, long long sBh,
      long long sCb, long long sCh, float alpha, int act)
{
    constexpr int WN  = CTA_N / 4;
    constexpr int NB  = WN / 8;
    constexpr int NP  = WN / 16;
    constexpr int BL  = CTA_N / 32;
    constexpr int ABYT   = 128 * 128;
    constexpr int STAGEB = ABYT + CTA_N * 128;

    extern __shared__ char smem[];
    uint32_t sbase = smem_u32(smem);

    int z = blockIdx.z, zb = z / HH, zh = z % HH;
    A += (long long)zb * sAb + (long long)zh * sAh;
    B += (long long)zb * sBb + (long long)zh * sBh;
    C += (long long)zb * sCb + (long long)zh * sCh;
    if (res) res += (long long)zb * sCb + (long long)zh * sCh;

    const int t = threadIdx.x;
    const int lane = t & 31;
    const int w = t >> 5, wm = w >> 2, wn = w & 3;
    const int m0 = blockIdx.y * 128;
    const int n0 = blockIdx.x * CTA_N;

    float acc[4][NB][4];
    #pragma unroll
    for (int i = 0; i < 4; i++)
        #pragma unroll
        for (int j = 0; j < NB; j++)
            #pragma unroll
            for (int q = 0; q < 4; q++) acc[i][j][q] = 0.f;

    const int KT = K / 32;
    float4 ra[4], rb[BL];

    const int lrA[4] = { (t + 0) >> 3, (t + 256) >> 3, (t + 512) >> 3, (t + 768) >> 3 };
    const int lkq = t & 7;

    auto load_regs = [&](int kt) {
        const float* Ak = A + kt * 32 + lkq * 4;
        #pragma unroll
        for (int i = 0; i < 4; i++)
            ra[i] = *(const float4*)(Ak + (long long)(m0 + lrA[i]) * lda);
        const float* Bk = B + kt * 32 + lkq * 4;
        #pragma unroll
        for (int i = 0; i < BL; i++)
            rb[i] = *(const float4*)(Bk + (long long)(n0 + ((t + i * 256) >> 3)) * ldb);
    };
    auto store_smem = [&](int st) {
        char* sA = smem + st * STAGEB;
        char* sB = sA + ABYT;
        #pragma unroll
        for (int i = 0; i < 4; i++) {
            int r = lrA[i];
            uint4 u = { f2tf(ra[i].x), f2tf(ra[i].y), f2tf(ra[i].z), f2tf(ra[i].w) };
            *(uint4*)(sA + r * 128 + ((lkq ^ (r & 7)) << 4)) = u;
        }
        #pragma unroll
        for (int i = 0; i < BL; i++) {
            int r = (t + i * 256) >> 3;
            uint4 u = { f2tf(rb[i].x), f2tf(rb[i].y), f2tf(rb[i].z), f2tf(rb[i].w) };
            *(uint4*)(sB + r * 128 + ((lkq ^ (r & 7)) << 4)) = u;
        }
    };

    load_regs(0);
    store_smem(0);
    __syncthreads();

    const int arow0 = wm * 64 + (lane & 7) + ((lane >> 3) & 1) * 8;
    const int ach0  = lane >> 4;
    const int brow0 = wn * WN + ((lane >> 4) & 1) * 8 + (lane & 7);
    const int bch0  = (lane >> 3) & 1;

    for (int kt = 0; kt < KT; kt++) {
        if (kt + 1 < KT) load_regs(kt + 1);

        uint32_t sA = sbase + (kt & 1) * STAGEB;
        uint32_t sB = sA + ABYT;
        #pragma unroll
        for (int ks = 0; ks < 4; ks++) {
            uint32_t a[4][4];
            #pragma unroll
            for (int mi = 0; mi < 4; mi++) {
                int r = arow0 + mi * 16;
                uint32_t ad = sA + r * 128 + (((ks * 2 + ach0) ^ (r & 7)) << 4);
                ldsm4(a[mi][0], a[mi][1], a[mi][2], a[mi][3], ad);
            }
            uint32_t b[NP][4];
            #pragma unroll
            for (int pi = 0; pi < NP; pi++) {
                int r = brow0 + pi * 16;
                uint32_t bd = sB + r * 128 + (((ks * 2 + bch0) ^ (r & 7)) << 4);
                ldsm4(b[pi][0], b[pi][1], b[pi][2], b[pi][3], bd);
            }
            #pragma unroll
            for (int mi = 0; mi < 4; mi++)
                #pragma unroll
                for (int ni = 0; ni < NB; ni++)
                    mma8(acc[mi][ni], a[mi], &b[ni >> 1][(ni & 1) * 2]);
        }

        if (kt + 1 < KT) store_smem((kt + 1) & 1);
        __syncthreads();
    }

    const int gid = lane >> 2;
    #pragma unroll
    for (int mi = 0; mi < 4; mi++) {
        #pragma unroll
        for (int ni = 0; ni < NB; ni++) {
            int r  = m0 + wm * 64 + mi * 16 + gid;
            int c  = n0 + wn * WN + ni * 8 + (lane & 3) * 2;
            float2 bv = bias ? *(const float2*)(bias + c) : make_float2(0.f, 0.f);
            #pragma unroll
            for (int half = 0; half < 2; half++) {
                int row = r + half * 8;
                float v0 = acc[mi][ni][half * 2 + 0] * alpha + bv.x;
                float v1 = acc[mi][ni][half * 2 + 1] * alpha + bv.y;
                if (act) { v0 = gelu_new(v0); v1 = gelu_new(v1); }
                if (res) {
                    float2 rv = *(const float2*)(res + (long long)row * ldc + c);
                    v0 += rv.x; v1 += rv.y;
                }
                float2 o; o.x = v0; o.y = v1;
                *(float2*)(C + (long long)row * ldc + c) = o;
            }
        }
    }
}

// ---------------------------------------------------------------------------
// Fused flash attention (tf32 mma, online softmax, exclude-self mask).
// Grid (NN/128, 1, BB*HH), 256 threads (8 warps x 16 q-rows).
// SMEM: sQ[0,32K) sP[32K,64K) sK[64K + st*16K) sV[96K + st*16K) = 128KB.
// All tiles: 64 cols of tf32 per row => 256B pitch, quad-XOR swizzle.
// ---------------------------------------------------------------------------
#define FCHUNK 64
__global__ void __launch_bounds__(256)
flash_attn(const float* __restrict__ qkv, const float* __restrict__ vt,
           float* __restrict__ ao)
{
    extern __shared__ char smem[];
    uint32_t sb = smem_u32(smem);
    const int t = threadIdx.x;
    const int lane = t & 31;
    const int w = t >> 5;
    const int q0 = blockIdx.x * 128;
    const int z = blockIdx.z;
    const int zb = z / HH, zh = z % HH;

    const float* Qg = qkv + (long long)zb * NN * 3 * DD + zh * HDIM;
    const float* Kg = Qg + DD;
    const float* Vt = vt + (long long)z * HDIM * NN;

    // Load Q tile (pre-scaled by 1/sqrt(HD)=0.125, exact) -> sQ
    #pragma unroll
    for (int i = 0; i < 8; i++) {
        int idx = t + i * 256;
        int r = idx >> 4, quad = idx & 15;
        float4 v = *(const float4*)(Qg + (long long)(q0 + r) * (3 * DD) + quad * 4);
        uint4 u = { f2tf(v.x * 0.125f), f2tf(v.y * 0.125f),
                    f2tf(v.z * 0.125f), f2tf(v.w * 0.125f) };
        *(uint4*)(smem + r * 256 + ((quad ^ (r & 7)) << 4)) = u;
    }
    __syncthreads();

    // Persistent Q fragments (m16 x k64 per warp)
    const int arow = w * 16 + (lane & 7) + ((lane >> 3) & 1) * 8;
    const int qsel = lane >> 4;
    uint32_t aQ[8][4];
    #pragma unroll
    for (int k8 = 0; k8 < 8; k8++) {
        uint32_t ad = sb + arow * 256 + (((k8 * 2 + qsel) ^ (arow & 7)) << 4);
        ldsm4(aQ[k8][0], aQ[k8][1], aQ[k8][2], aQ[k8][3], ad);
    }

    const int brow = ((lane >> 4) & 1) * 8 + (lane & 7);
    const int bsel = (lane >> 3) & 1;
    const int gid = lane >> 2, cq = lane & 3;
    const int row0 = q0 + w * 16 + gid;       // my fragment rows: row0, row0+8

    float m0 = -1e30f, m1 = -1e30f, l0 = 0.f, l1 = 0.f;
    float accO[8][4];
    #pragma unroll
    for (int j = 0; j < 8; j++)
        #pragma unroll
        for (int q = 0; q < 4; q++) accO[j][q] = 0.f;

    float4 rk[4], rv[4];
    auto load_regs = [&](int ch) {
        int c0 = ch * FCHUNK;
        #pragma unroll
        for (int i = 0; i < 4; i++) {
            int idx = t + i * 256;
            int r = idx >> 4, quad = idx & 15;
            rk[i] = *(const float4*)(Kg + (long long)(c0 + r) * (3 * DD) + quad * 4);
            rv[i] = *(const float4*)(Vt + (long long)r * NN + c0 + quad * 4);
        }
    };
    auto store_smem = [&](int st) {
        char* sK = smem + 65536 + st * 16384;
        char* sV = smem + 98304 + st * 16384;
        #pragma unroll
        for (int i = 0; i < 4; i++) {
            int idx = t + i * 256;
            int r = idx >> 4, quad = idx & 15;
            int so = r * 256 + ((quad ^ (r & 7)) << 4);
            uint4 uk = { f2tf(rk[i].x), f2tf(rk[i].y), f2tf(rk[i].z), f2tf(rk[i].w) };
            *(uint4*)(sK + so) = uk;
            uint4 uv = { f2tf(rv[i].x), f2tf(rv[i].y), f2tf(rv[i].z), f2tf(rv[i].w) };
            *(uint4*)(sV + so) = uv;
        }
    };

    load_regs(0);
    store_smem(0);
    __syncthreads();

    const int NCH = NN / FCHUNK;   // 32
    for (int ch = 0; ch < NCH; ch++) {
        if (ch + 1 < NCH) load_regs(ch + 1);
        int st = ch & 1;
        uint32_t sK = sb + 65536 + st * 16384;
        uint32_t sV = sb + 98304 + st * 16384;

        // ---- S = Qs @ K^T (scale pre-folded into Q)
        float accS[8][4];
        #pragma unroll
        for (int j = 0; j < 8; j++)
            #pragma unroll
            for (int q = 0; q < 4; q++) accS[j][q] = 0.f;

        #pragma unroll
        for (int k8 = 0; k8 < 8; k8++) {
            uint32_t b[4][4];
            #pragma unroll
            for (int g = 0; g < 4; g++) {
                int r = g * 16 + brow;
                uint32_t bd = sK + r * 256 + (((k8 * 2 + bsel) ^ (r & 7)) << 4);
                ldsm4(b[g][0], b[g][1], b[g][2], b[g][3], bd);
            }
            #pragma unroll
            for (int j = 0; j < 8; j++)
                mma8(accS[j], aQ[k8], &b[j >> 1][(j & 1) * 2]);
        }

        // ---- exclude-self mask
        int c0 = ch * FCHUNK;
        #pragma unroll
        for (int j = 0; j < 8; j++) {
            int col = c0 + j * 8 + cq * 2;
            if (col     == row0    ) accS[j][0] = -1e30f;
            if (col + 1 == row0    ) accS[j][1] = -1e30f;
            if (col     == row0 + 8) accS[j][2] = -1e30f;
            if (col + 1 == row0 + 8) accS[j][3] = -1e30f;
        }

        // ---- online softmax
        float cm0 = -1e30f, cm1 = -1e30f;
        #pragma unroll
        for (int j = 0; j < 8; j++) {
            cm0 = fmaxf(cm0, fmaxf(accS[j][0], accS[j][1]));
            cm1 = fmaxf(cm1, fmaxf(accS[j][2], accS[j][3]));
        }
        cm0 = fmaxf(cm0, __shfl_xor_sync(0xffffffffu, cm0, 1));
        cm0 = fmaxf(cm0, __shfl_xor_sync(0xffffffffu, cm0, 2));
        cm1 = fmaxf(cm1, __shfl_xor_sync(0xffffffffu, cm1, 1));
        cm1 = fmaxf(cm1, __shfl_xor_sync(0xffffffffu, cm1, 2));
        float nm0 = fmaxf(m0, cm0), nm1 = fmaxf(m1, cm1);
        float sc0 = __expf(m0 - nm0), sc1 = __expf(m1 - nm1);
        m0 = nm0; m1 = nm1;

        float ps0 = 0.f, ps1 = 0.f;
        #pragma unroll
        for (int j = 0; j < 8; j++) {
            accS[j][0] = __expf(accS[j][0] - nm0);
            accS[j][1] = __expf(accS[j][1] - nm0);
            accS[j][2] = __expf(accS[j][2] - nm1);
            accS[j][3] = __expf(accS[j][3] - nm1);
            ps0 += accS[j][0] + accS[j][1];
            ps1 += accS[j][2] + accS[j][3];
        }
        ps0 += __shfl_xor_sync(0xffffffffu, ps0, 1);
        ps0 += __shfl_xor_sync(0xffffffffu, ps0, 2);
        ps1 += __shfl_xor_sync(0xffffffffu, ps1, 1);
        ps1 += __shfl_xor_sync(0xffffffffu, ps1, 2);
        l0 = l0 * sc0 + ps0;
        l1 = l1 * sc1 + ps1;

        #pragma unroll
        for (int j = 0; j < 8; j++) {
            accO[j][0] *= sc0; accO[j][1] *= sc0;
            accO[j][2] *= sc1; accO[j][3] *= sc1;
        }

        // ---- P -> sP (tf32) in A-operand layout; warp-private region
        int pr0 = w * 16 + gid, pr1 = pr0 + 8;
        #pragma unroll
        for (int j = 0; j < 8; j++) {
            int quad = 2 * j + (cq >> 1);
            int off8 = (cq & 1) * 8;
            uint2 u0 = { f2tf(accS[j][0]), f2tf(accS[j][1]) };
            *(uint2*)(smem + 32768 + pr0 * 256 + ((quad ^ (pr0 & 7)) << 4) + off8) = u0;
            uint2 u1 = { f2tf(accS[j][2]), f2tf(accS[j][3]) };
            *(uint2*)(smem + 32768 + pr1 * 256 + ((quad ^ (pr1 & 7)) << 4) + off8) = u1;
        }
        __syncwarp();

        // ---- O += P @ V
        #pragma unroll
        for (int k8 = 0; k8 < 8; k8++) {
            uint32_t aP[4];
            uint32_t ad = sb + 32768 + arow * 256 + (((k8 * 2 + qsel) ^ (arow & 7)) << 4);
            ldsm4(aP[0], aP[1], aP[2], aP[3], ad);
            uint32_t bv[4][4];
            #pragma unroll
            for (int g = 0; g < 4; g++) {
                int r = g * 16 + brow;
                uint32_t bd = sV + r * 256 + (((k8 * 2 + bsel) ^ (r & 7)) << 4);
                ldsm4(bv[g][0], bv[g][1], bv[g][2], bv[g][3], bd);
            }
            #pragma unroll
            for (int j = 0; j < 8; j++)
                mma8(accO[j], aP, &bv[j >> 1][(j & 1) * 2]);
        }
        __syncwarp();

        if (ch + 1 < NCH) store_smem((ch + 1) & 1);
        __syncthreads();
    }

    // ---- write O / l
    float inv0 = 1.0f / l0, inv1 = 1.0f / l1;
    float* ao0 = ao + ((long long)zb * NN + row0) * DD + zh * HDIM;
    float* ao1 = ao0 + 8 * DD;
    #pragma unroll
    for (int j = 0; j < 8; j++) {
        int c = j * 8 + cq * 2;
        float2 v0 = { accO[j][0] * inv0, accO[j][1] * inv0 };
        *(float2*)(ao0 + c) = v0;
        float2 v1 = { accO[j][2] * inv1, accO[j][3] * inv1 };
        *(float2*)(ao1 + c) = v1;
    }
}

// ---------------------------------------------------------------------------
__global__ void transpose_k(const float* __restrict__ src, float* __restrict__ dst,
                            int lds, int ldd,
                            long long szb, long long szh, long long dzb, long long dzh)
{
    __shared__ float tile[32][33];
    int z = blockIdx.z, zb = z / HH, zh = z % HH;
    src += (long long)zb * szb + (long long)zh * szh;
    dst += (long long)zb * dzb + (long long)zh * dzh;
    int c0 = blockIdx.x * 32, r0 = blockIdx.y * 32;
    int tx = threadIdx.x, ty = threadIdx.y;   // 32 x 8
    #pragma unroll
    for (int i = 0; i < 32; i += 8)
        tile[ty + i][tx] = src[(long long)(r0 + ty + i) * lds + c0 + tx];
    __syncthreads();
    #pragma unroll
    for (int i = 0; i < 32; i += 8)
        dst[(long long)(c0 + ty + i) * ldd + r0 + tx] = tile[tx][ty + i];
}

__global__ void addpos_k(const float* __restrict__ e, const float* __restrict__ p,
                         float* __restrict__ h)
{
    long long i = (long long)blockIdx.x * 256 + threadIdx.x;
    long long nd = i % ((long long)NN * DD);
    h[i] = e[i] + p[nd];
}

__global__ void layernorm_k(const float* __restrict__ x, const float* __restrict__ g,
                            const float* __restrict__ b, float* __restrict__ y)
{
    int row = blockIdx.x;
    int t = threadIdx.x;
    const float* xr = x + (long long)row * DD;
    float4 v = *(const float4*)(xr + t * 4);
    float s  = v.x + v.y + v.z + v.w;
    float ss = v.x*v.x + v.y*v.y + v.z*v.z + v.w*v.w;
    #pragma unroll
    for (int o = 16; o; o >>= 1) {
        s  += __shfl_xor_sync(0xffffffffu, s,  o);
        ss += __shfl_xor_sync(0xffffffffu, ss, o);
    }
    __shared__ float r1[4], r2[4];
    int wid = t >> 5, lane = t & 31;
    if (lane == 0) { r1[wid] = s; r2[wid] = ss; }
    __syncthreads();
    float sum   = r1[0] + r1[1] + r1[2] + r1[3];
    float sumsq = r2[0] + r2[1] + r2[2] + r2[3];
    float mu   = sum * (1.0f / DD);
    float var  = sumsq * (1.0f / DD) - mu * mu;
    float rstd = rsqrtf(var + 1e-5f);
    float4 gg = *(const float4*)(g + t * 4);
    float4 bb = *(const float4*)(b + t * 4);
    float4 o;
    o.x = (v.x - mu) * rstd * gg.x + bb.x;
    o.y = (v.y - mu) * rstd * gg.y + bb.y;
    o.z = (v.z - mu) * rstd * gg.z + bb.z;
    o.w = (v.w - mu) * rstd * gg.w + bb.w;
    *(float4*)(y + (long long)row * DD + t * 4) = o;
}

// ---------------------------------------------------------------------------
extern "C" void kernel_launch(void* const* d_in, const int* in_sizes, int n_in,
                              void* d_out, int out_size)
{
    const float* emb      = (const float*)d_in[0];
    const float* pos      = (const float*)d_in[1];
    const float* c_attn_w = (const float*)d_in[2];
    const float* c_attn_b = (const float*)d_in[3];
    const float* out_w    = (const float*)d_in[4];
    const float* out_b    = (const float*)d_in[5];
    const float* ln1_g    = (const float*)d_in[6];
    const float* ln1_b    = (const float*)d_in[7];
    const float* c_fc_w   = (const float*)d_in[8];
    const float* c_fc_b   = (const float*)d_in[9];
    const float* c_proj_w = (const float*)d_in[10];
    const float* c_proj_b = (const float*)d_in[11];
    const float* ln2_g    = (const float*)d_in[12];
    const float* ln2_b    = (const float*)d_in[13];
    (void)in_sizes; (void)n_in; (void)out_size;

    float *h_, *x_, *qkv_, *ao_, *fc_, *wt_, *vt_;
    cudaGetSymbolAddress((void**)&h_,   g_h);
    cudaGetSymbolAddress((void**)&x_,   g_x);
    cudaGetSymbolAddress((void**)&qkv_, g_qkv);
    cudaGetSymbolAddress((void**)&ao_,  g_ao);
    cudaGetSymbolAddress((void**)&fc_,  g_fc);
    cudaGetSymbolAddress((void**)&wt_,  g_wt);
    cudaGetSymbolAddress((void**)&vt_,  g_vt);

    const int SM128 = 2 * (128 + 128) * 128;   // 65536
    const int SMFL  = 131072;
    cudaFuncSetAttribute(mgemm<128>, cudaFuncAttributeMaxDynamicSharedMemorySize, SM128);
    cudaFuncSetAttribute(flash_attn, cudaFuncAttributeMaxDynamicSharedMemorySize, SMFL);

    dim3 tb(32, 8);

    addpos_k<<<(TOK * DD) / 256, 256>>>(emb, pos, h_);

    for (int l = 0; l < LL; l++) {
        const float* aw = c_attn_w + (long long)l * DD * 3 * DD;
        const float* ab = c_attn_b + (long long)l * 3 * DD;
        const float* ow = out_w    + (long long)l * DD * DD;
        const float* ob = out_b    + (long long)l * DD;
        const float* fw = c_fc_w   + (long long)l * DD * 4 * DD;
        const float* fb = c_fc_b   + (long long)l * 4 * DD;
        const float* pw = c_proj_w + (long long)l * 4 * DD * DD;
        const float* pb = c_proj_b + (long long)l * DD;

        // Weight transposes -> K-major B operands
        transpose_k<<<dim3(3*DD/32, DD/32, 1), tb>>>(aw, wt_ + AW_T, 3*DD, DD, 0,0,0,0);
        transpose_k<<<dim3(DD/32,   DD/32, 1), tb>>>(ow, wt_ + OW_T, DD,   DD, 0,0,0,0);
        transpose_k<<<dim3(4*DD/32, DD/32, 1), tb>>>(fw, wt_ + FW_T, 4*DD, DD, 0,0,0,0);
        transpose_k<<<dim3(DD/32, 4*DD/32, 1), tb>>>(pw, wt_ + PW_T, DD, 4*DD, 0,0,0,0);

        // x = LN1(h)
        layernorm_k<<<TOK, 128>>>(h_, ln1_g + l * DD, ln1_b + l * DD, x_);

        // qkv = x @ c_attn_w + b     [4096,1536] K=512
        mgemm<128><<<dim3(3*DD/128, TOK/128, 1), 256, SM128>>>(
            x_, wt_ + AW_T, ab, nullptr, qkv_,
            DD, DD, DD, 3*DD, 0,0,0,0,0,0, 1.0f, 0);

        // vt[b*h][hd][n] = V^T
        transpose_k<<<dim3(HDIM/32, NN/32, BB*HH), tb>>>(
            qkv_ + 2*DD, vt_, 3*DD, NN,
            (long long)NN*3*DD, HDIM,
            (long long)HH*HDIM*NN, (long long)HDIM*NN);

        // fused attention -> ao (heads merged)
        flash_attn<<<dim3(NN/128, 1, BB*HH), 256, SMFL>>>(qkv_, vt_, ao_);

        // h = ao @ out_w + out_b + h   [4096,512] K=512
        mgemm<128><<<dim3(DD/128, TOK/128, 1), 256, SM128>>>(
            ao_, wt_ + OW_T, ob, h_, h_,
            DD, DD, DD, DD, 0,0,0,0,0,0, 1.0f, 0);

        // x = LN2(h)
        layernorm_k<<<TOK, 128>>>(h_, ln2_g + l * DD, ln2_b + l * DD, x_);

        // fc = gelu(x @ c_fc_w + b)  [4096,2048] K=512
        mgemm<128><<<dim3(4*DD/128, TOK/128, 1), 256, SM128>>>(
            x_, wt_ + FW_T, fb, nullptr, fc_,
            DD, DD, DD, 4*DD, 0,0,0,0,0,0, 1.0f, 1);

        // h = fc @ c_proj_w + b + h  [4096,512] K=2048
        float* dst = (l == LL - 1) ? (float*)d_out : h_;
        mgemm<128><<<dim3(DD/128, TOK/128, 1), 256, SM128>>>(
            fc_, wt_ + PW_T, pb, h_, dst,
            4*DD, 4*DD, 4*DD, DD, 0,0,0,0,0,0, 1.0f, 0);
    }
}

// round 5
// speedup vs baseline: 4.2171x; 1.2062x over previous
#include <cuda_runtime.h>
#include <cstdint>
#include <math.h>

// Problem constants
#define BB 2
#define NN 2048
#define DD 512
#define HH 8
#define HDIM 64
#define LL 2
#define TOK (BB*NN)          // 4096 rows

// Scratch (device globals — no allocation allowed)
__device__ float g_h  [(size_t)TOK * DD];
__device__ float g_x  [(size_t)TOK * DD];
__device__ float g_qkv[(size_t)TOK * 3 * DD];
__device__ float g_ao [(size_t)TOK * DD];
__device__ float g_fc [(size_t)TOK * 4 * DD];
__device__ float g_wt [3145728];                      // transposed weights (one layer)
__device__ float g_vt [(size_t)BB * HH * HDIM * NN];  // V transposed [b*h][hd][n]

#define AW_T 0          // [1536,512]
#define OW_T 786432     // [512,512]
#define FW_T 1048576    // [2048,512]
#define PW_T 2097152    // [512,2048]

// ---------------------------------------------------------------------------
__device__ __forceinline__ uint32_t smem_u32(const void* p) {
    uint32_t a;
    asm("{ .reg .u64 t; cvta.to.shared.u64 t, %1; cvt.u32.u64 %0, t; }" : "=r"(a) : "l"(p));
    return a;
}
__device__ __forceinline__ void cpa16(uint32_t saddr, const void* g) {
    asm volatile("cp.async.cg.shared.global [%0], [%1], 16;" :: "r"(saddr), "l"(g));
}
#define CP_COMMIT() asm volatile("cp.async.commit_group;" ::: "memory")
#define CP_WAIT(n)  asm volatile("cp.async.wait_group %0;" :: "n"(n) : "memory")
__device__ __forceinline__ void ldsm4(uint32_t& r0, uint32_t& r1, uint32_t& r2, uint32_t& r3,
                                      uint32_t addr) {
    asm volatile("ldmatrix.sync.aligned.m8n8.x4.shared.b16 {%0,%1,%2,%3}, [%4];"
                 : "=r"(r0), "=r"(r1), "=r"(r2), "=r"(r3) : "r"(addr));
}
__device__ __forceinline__ void mma8(float* d, const uint32_t* a, const uint32_t* b) {
    asm volatile(
        "mma.sync.aligned.m16n8k8.row.col.f32.tf32.tf32.f32 "
        "{%0,%1,%2,%3}, {%4,%5,%6,%7}, {%8,%9}, {%0,%1,%2,%3};"
        : "+f"(d[0]), "+f"(d[1]), "+f"(d[2]), "+f"(d[3])
        : "r"(a[0]), "r"(a[1]), "r"(a[2]), "r"(a[3]), "r"(b[0]), "r"(b[1]));
}
__device__ __forceinline__ float gelu_new(float x) {
    float x3 = x * x * x;
    return 0.5f * x * (1.0f + tanhf(0.7978845608028654f * (x + 0.044715f * x3)));
}

// ---------------------------------------------------------------------------
// tf32 tensor-core GEMM, cp.async 3-stage pipeline, raw fp32 operands.
// C[M,N] = alpha*(A @ B^T) + bias (+GELU) (+res)
// A: [M,K] K-major (lda).  B: [N,K] K-major (ldb).  CTA tile 128 x CTA_N.
// ---------------------------------------------------------------------------
template<int CTA_N>
__global__ void __launch_bounds__(256, 2)
mgemm(const float* __restrict__ A, const float* __restrict__ B,
      const float* __restrict__ bias, const float* res, float* __restrict__ C,
      int K, int lda, int ldb, int ldc,
      long long sAb, long long sAh, long long sBb, long long sBh,
      long long sCb, long long sCh, float alpha, int act)
{
    constexpr int WN  = CTA_N / 4;
    constexpr int NB  = WN / 8;
    constexpr int NP  = WN / 16;
    constexpr int BL  = CTA_N / 32;      // B cp.async chunks per thread
    constexpr int ABYT   = 128 * 128;
    constexpr int STAGEB = ABYT + CTA_N * 128;
    constexpr int NS  = 3;

    extern __shared__ char smem[];
    uint32_t sbase = smem_u32(smem);

    int z = blockIdx.z, zb = z / HH, zh = z % HH;
    A += (long long)zb * sAb + (long long)zh * sAh;
    B += (long long)zb * sBb + (long long)zh * sBh;
    C += (long long)zb * sCb + (long long)zh * sCh;
    if (res) res += (long long)zb * sCb + (long long)zh * sCh;

    const int t = threadIdx.x;
    const int lane = t & 31;
    const int w = t >> 5, wm = w >> 2, wn = w & 3;
    const int m0 = blockIdx.y * 128;
    const int n0 = blockIdx.x * CTA_N;

    float acc[4][NB][4];
    #pragma unroll
    for (int i = 0; i < 4; i++)
        #pragma unroll
        for (int j = 0; j < NB; j++)
            #pragma unroll
            for (int q = 0; q < 4; q++) acc[i][j][q] = 0.f;

    const int KT = K / 32;
    const int lkq = t & 7;

    auto issue = [&](int kt) {
        int st = kt % NS;
        uint32_t sA = sbase + st * STAGEB;
        const float* Ak = A + kt * 32 + lkq * 4;
        #pragma unroll
        for (int i = 0; i < 4; i++) {
            int r = (t + i * 256) >> 3;
            cpa16(sA + r * 128 + ((lkq ^ (r & 7)) << 4),
                  Ak + (long long)(m0 + r) * lda);
        }
        uint32_t sB = sA + ABYT;
        const float* Bk = B + kt * 32 + lkq * 4;
        #pragma unroll
        for (int i = 0; i < BL; i++) {
            int r = (t + i * 256) >> 3;
            cpa16(sB + r * 128 + ((lkq ^ (r & 7)) << 4),
                  Bk + (long long)(n0 + r) * ldb);
        }
    };

    #pragma unroll
    for (int s = 0; s < NS - 1; s++) {
        if (s < KT) issue(s);
        CP_COMMIT();
    }

    const int arow0 = wm * 64 + (lane & 7) + ((lane >> 3) & 1) * 8;
    const int ach0  = lane >> 4;
    const int brow0 = wn * WN + ((lane >> 4) & 1) * 8 + (lane & 7);
    const int bch0  = (lane >> 3) & 1;

    for (int kt = 0; kt < KT; kt++) {
        if (kt + NS - 1 < KT) issue(kt + NS - 1);
        CP_COMMIT();
        CP_WAIT(NS - 1);
        __syncthreads();

        uint32_t sA = sbase + (kt % NS) * STAGEB;
        uint32_t sB = sA + ABYT;
        #pragma unroll
        for (int ks = 0; ks < 4; ks++) {
            uint32_t a[4][4];
            #pragma unroll
            for (int mi = 0; mi < 4; mi++) {
                int r = arow0 + mi * 16;
                uint32_t ad = sA + r * 128 + (((ks * 2 + ach0) ^ (r & 7)) << 4);
                ldsm4(a[mi][0], a[mi][1], a[mi][2], a[mi][3], ad);
            }
            uint32_t b[NP][4];
            #pragma unroll
            for (int pi = 0; pi < NP; pi++) {
                int r = brow0 + pi * 16;
                uint32_t bd = sB + r * 128 + (((ks * 2 + bch0) ^ (r & 7)) << 4);
                ldsm4(b[pi][0], b[pi][1], b[pi][2], b[pi][3], bd);
            }
            #pragma unroll
            for (int mi = 0; mi < 4; mi++)
                #pragma unroll
                for (int ni = 0; ni < NB; ni++)
                    mma8(acc[mi][ni], a[mi], &b[ni >> 1][(ni & 1) * 2]);
        }
        __syncthreads();
    }

    const int gid = lane >> 2;
    #pragma unroll
    for (int mi = 0; mi < 4; mi++) {
        #pragma unroll
        for (int ni = 0; ni < NB; ni++) {
            int r  = m0 + wm * 64 + mi * 16 + gid;
            int c  = n0 + wn * WN + ni * 8 + (lane & 3) * 2;
            float2 bv = bias ? *(const float2*)(bias + c) : make_float2(0.f, 0.f);
            #pragma unroll
            for (int half = 0; half < 2; half++) {
                int row = r + half * 8;
                float v0 = acc[mi][ni][half * 2 + 0] * alpha + bv.x;
                float v1 = acc[mi][ni][half * 2 + 1] * alpha + bv.y;
                if (act) { v0 = gelu_new(v0); v1 = gelu_new(v1); }
                if (res) {
                    float2 rv = *(const float2*)(res + (long long)row * ldc + c);
                    v0 += rv.x; v1 += rv.y;
                }
                float2 o; o.x = v0; o.y = v1;
                *(float2*)(C + (long long)row * ldc + c) = o;
            }
        }
    }
}

// ---------------------------------------------------------------------------
// Fused flash attention (tf32 mma, online softmax, exclude-self mask).
// Grid (NN/128, 1, BB*HH), 256 threads (8 warps x 16 q-rows).
// SMEM (96KB): sQ/sP alias [0,32K); K stage s at 32K+s*32K; V at 48K+s*32K.
// cp.async loads; raw fp32 operands; 0.125 scale applied post-MMA (exact).
// ---------------------------------------------------------------------------
#define FCHUNK 64
__global__ void __launch_bounds__(256)
flash_attn(const float* __restrict__ qkv, const float* __restrict__ vt,
           float* __restrict__ ao)
{
    extern __shared__ char smem[];
    uint32_t sb = smem_u32(smem);
    const int t = threadIdx.x;
    const int lane = t & 31;
    const int w = t >> 5;
    const int q0 = blockIdx.x * 128;
    const int z = blockIdx.z;
    const int zb = z / HH, zh = z % HH;

    const float* Qg = qkv + (long long)zb * NN * 3 * DD + zh * HDIM;
    const float* Kg = Qg + DD;
    const float* Vt = vt + (long long)z * HDIM * NN;

    const int lr16 = t >> 4;           // row for 16-chunk loads (Q: 8 iters)
    const int lq16 = t & 15;           // quad

    auto issue_kv = [&](int ch) {
        int st = ch & 1;
        int c0 = ch * FCHUNK;
        uint32_t sK = sb + 32768 + st * 32768;
        uint32_t sV = sK + 16384;
        #pragma unroll
        for (int i = 0; i < 4; i++) {
            int idx = t + i * 256;
            int r = idx >> 4, quad = idx & 15;
            uint32_t so = r * 256 + ((quad ^ (r & 7)) << 4);
            cpa16(sK + so, Kg + (long long)(c0 + r) * (3 * DD) + quad * 4);
            cpa16(sV + so, Vt + (long long)r * NN + c0 + quad * 4);
        }
    };

    // Q -> sQ (group 1), KV chunk 0 (group 2)
    #pragma unroll
    for (int i = 0; i < 8; i++) {
        int idx = t + i * 256;
        int r = idx >> 4, quad = idx & 15;
        cpa16(sb + r * 256 + ((quad ^ (r & 7)) << 4),
              Qg + (long long)(q0 + r) * (3 * DD) + quad * 4);
    }
    CP_COMMIT();
    issue_kv(0);
    CP_COMMIT();
    CP_WAIT(1);          // Q resident
    __syncthreads();

    // Persistent Q fragments (m16 x k64 per warp)
    const int arow = w * 16 + (lane & 7) + ((lane >> 3) & 1) * 8;
    const int qsel = lane >> 4;
    uint32_t aQ[8][4];
    #pragma unroll
    for (int k8 = 0; k8 < 8; k8++) {
        uint32_t ad = sb + arow * 256 + (((k8 * 2 + qsel) ^ (arow & 7)) << 4);
        ldsm4(aQ[k8][0], aQ[k8][1], aQ[k8][2], aQ[k8][3], ad);
    }
    __syncthreads();     // all warps' Q frags loaded before sP overwrites region

    const int brow = ((lane >> 4) & 1) * 8 + (lane & 7);
    const int bsel = (lane >> 3) & 1;
    const int gid = lane >> 2, cq = lane & 3;
    const int row0 = q0 + w * 16 + gid;

    float m0 = -1e30f, m1 = -1e30f, l0 = 0.f, l1 = 0.f;
    float accO[8][4];
    #pragma unroll
    for (int j = 0; j < 8; j++)
        #pragma unroll
        for (int q = 0; q < 4; q++) accO[j][q] = 0.f;

    const int NCH = NN / FCHUNK;   // 32
    for (int ch = 0; ch < NCH; ch++) {
        if (ch + 1 < NCH) issue_kv(ch + 1);
        CP_COMMIT();
        CP_WAIT(1);
        __syncthreads();

        int st = ch & 1;
        uint32_t sK = sb + 32768 + st * 32768;
        uint32_t sV = sK + 16384;

        // ---- S = Q @ K^T (raw tf32), scale 0.125 applied after
        float accS[8][4];
        #pragma unroll
        for (int j = 0; j < 8; j++)
            #pragma unroll
            for (int q = 0; q < 4; q++) accS[j][q] = 0.f;

        #pragma unroll
        for (int k8 = 0; k8 < 8; k8++) {
            uint32_t b[4][4];
            #pragma unroll
            for (int g = 0; g < 4; g++) {
                int r = g * 16 + brow;
                uint32_t bd = sK + r * 256 + (((k8 * 2 + bsel) ^ (r & 7)) << 4);
                ldsm4(b[g][0], b[g][1], b[g][2], b[g][3], bd);
            }
            #pragma unroll
            for (int j = 0; j < 8; j++)
                mma8(accS[j], aQ[k8], &b[j >> 1][(j & 1) * 2]);
        }

        // ---- scale (exact: power of 2) + exclude-self mask
        int c0 = ch * FCHUNK;
        #pragma unroll
        for (int j = 0; j < 8; j++) {
            accS[j][0] *= 0.125f; accS[j][1] *= 0.125f;
            accS[j][2] *= 0.125f; accS[j][3] *= 0.125f;
            int col = c0 + j * 8 + cq * 2;
            if (col     == row0    ) accS[j][0] = -1e30f;
            if (col + 1 == row0    ) accS[j][1] = -1e30f;
            if (col     == row0 + 8) accS[j][2] = -1e30f;
            if (col + 1 == row0 + 8) accS[j][3] = -1e30f;
        }

        // ---- online softmax
        float cm0 = -1e30f, cm1 = -1e30f;
        #pragma unroll
        for (int j = 0; j < 8; j++) {
            cm0 = fmaxf(cm0, fmaxf(accS[j][0], accS[j][1]));
            cm1 = fmaxf(cm1, fmaxf(accS[j][2], accS[j][3]));
        }
        cm0 = fmaxf(cm0, __shfl_xor_sync(0xffffffffu, cm0, 1));
        cm0 = fmaxf(cm0, __shfl_xor_sync(0xffffffffu, cm0, 2));
        cm1 = fmaxf(cm1, __shfl_xor_sync(0xffffffffu, cm1, 1));
        cm1 = fmaxf(cm1, __shfl_xor_sync(0xffffffffu, cm1, 2));
        float nm0 = fmaxf(m0, cm0), nm1 = fmaxf(m1, cm1);
        float sc0 = __expf(m0 - nm0), sc1 = __expf(m1 - nm1);
        m0 = nm0; m1 = nm1;

        float ps0 = 0.f, ps1 = 0.f;
        #pragma unroll
        for (int j = 0; j < 8; j++) {
            accS[j][0] = __expf(accS[j][0] - nm0);
            accS[j][1] = __expf(accS[j][1] - nm0);
            accS[j][2] = __expf(accS[j][2] - nm1);
            accS[j][3] = __expf(accS[j][3] - nm1);
            ps0 += accS[j][0] + accS[j][1];
            ps1 += accS[j][2] + accS[j][3];
        }
        ps0 += __shfl_xor_sync(0xffffffffu, ps0, 1);
        ps0 += __shfl_xor_sync(0xffffffffu, ps0, 2);
        ps1 += __shfl_xor_sync(0xffffffffu, ps1, 1);
        ps1 += __shfl_xor_sync(0xffffffffu, ps1, 2);
        l0 = l0 * sc0 + ps0;
        l1 = l1 * sc1 + ps1;

        #pragma unroll
        for (int j = 0; j < 8; j++) {
            accO[j][0] *= sc0; accO[j][1] *= sc0;
            accO[j][2] *= sc1; accO[j][3] *= sc1;
        }

        // ---- P -> sP (aliases sQ region; rows warp-private)
        int pr0 = w * 16 + gid, pr1 = pr0 + 8;
        #pragma unroll
        for (int j = 0; j < 8; j++) {
            int quad = 2 * j + (cq >> 1);
            int off8 = (cq & 1) * 8;
            float2 u0 = { accS[j][0], accS[j][1] };
            *(float2*)(smem + pr0 * 256 + ((quad ^ (pr0 & 7)) << 4) + off8) = u0;
            float2 u1 = { accS[j][2], accS[j][3] };
            *(float2*)(smem + pr1 * 256 + ((quad ^ (pr1 & 7)) << 4) + off8) = u1;
        }
        __syncwarp();

        // ---- O += P @ V
        #pragma unroll
        for (int k8 = 0; k8 < 8; k8++) {
            uint32_t aP[4];
            uint32_t ad = sb + arow * 256 + (((k8 * 2 + qsel) ^ (arow & 7)) << 4);
            ldsm4(aP[0], aP[1], aP[2], aP[3], ad);
            uint32_t bv[4][4];
            #pragma unroll
            for (int g = 0; g < 4; g++) {
                int r = g * 16 + brow;
                uint32_t bd = sV + r * 256 + (((k8 * 2 + bsel) ^ (r & 7)) << 4);
                ldsm4(bv[g][0], bv[g][1], bv[g][2], bv[g][3], bd);
            }
            #pragma unroll
            for (int j = 0; j < 8; j++)
                mma8(accO[j], aP, &bv[j >> 1][(j & 1) * 2]);
        }
        __syncthreads();
    }
    (void)lr16; (void)lq16;

    // ---- write O
    float inv0 = 1.0f / l0, inv1 = 1.0f / l1;
    float* ao0 = ao + ((long long)zb * NN + row0) * DD + zh * HDIM;
    float* ao1 = ao0 + 8 * DD;
    #pragma unroll
    for (int j = 0; j < 8; j++) {
        int c = j * 8 + cq * 2;
        float2 v0 = { accO[j][0] * inv0, accO[j][1] * inv0 };
        *(float2*)(ao0 + c) = v0;
        float2 v1 = { accO[j][2] * inv1, accO[j][3] * inv1 };
        *(float2*)(ao1 + c) = v1;
    }
}

// ---------------------------------------------------------------------------
__global__ void transpose_k(const float* __restrict__ src, float* __restrict__ dst,
                            int lds, int ldd,
                            long long szb, long long szh, long long dzb, long long dzh)
{
    __shared__ float tile[32][33];
    int z = blockIdx.z, zb = z / HH, zh = z % HH;
    src += (long long)zb * szb + (long long)zh * szh;
    dst += (long long)zb * dzb + (long long)zh * dzh;
    int c0 = blockIdx.x * 32, r0 = blockIdx.y * 32;
    int tx = threadIdx.x, ty = threadIdx.y;   // 32 x 8
    #pragma unroll
    for (int i = 0; i < 32; i += 8)
        tile[ty + i][tx] = src[(long long)(r0 + ty + i) * lds + c0 + tx];
    __syncthreads();
    #pragma unroll
    for (int i = 0; i < 32; i += 8)
        dst[(long long)(c0 + ty + i) * ldd + r0 + tx] = tile[tx][ty + i];
}

__global__ void addpos_k(const float* __restrict__ e, const float* __restrict__ p,
                         float* __restrict__ h)
{
    long long i = (long long)blockIdx.x * 256 + threadIdx.x;
    long long nd = i % ((long long)NN * DD);
    h[i] = e[i] + p[nd];
}

__global__ void layernorm_k(const float* __restrict__ x, const float* __restrict__ g,
                            const float* __restrict__ b, float* __restrict__ y)
{
    int row = blockIdx.x;
    int t = threadIdx.x;
    const float* xr = x + (long long)row * DD;
    float4 v = *(const float4*)(xr + t * 4);
    float s  = v.x + v.y + v.z + v.w;
    float ss = v.x*v.x + v.y*v.y + v.z*v.z + v.w*v.w;
    #pragma unroll
    for (int o = 16; o; o >>= 1) {
        s  += __shfl_xor_sync(0xffffffffu, s,  o);
        ss += __shfl_xor_sync(0xffffffffu, ss, o);
    }
    __shared__ float r1[4], r2[4];
    int wid = t >> 5, lane = t & 31;
    if (lane == 0) { r1[wid] = s; r2[wid] = ss; }
    __syncthreads();
    float sum   = r1[0] + r1[1] + r1[2] + r1[3];
    float sumsq = r2[0] + r2[1] + r2[2] + r2[3];
    float mu   = sum * (1.0f / DD);
    float var  = sumsq * (1.0f / DD) - mu * mu;
    float rstd = rsqrtf(var + 1e-5f);
    float4 gg = *(const float4*)(g + t * 4);
    float4 bb = *(const float4*)(b + t * 4);
    float4 o;
    o.x = (v.x - mu) * rstd * gg.x + bb.x;
    o.y = (v.y - mu) * rstd * gg.y + bb.y;
    o.z = (v.z - mu) * rstd * gg.z + bb.z;
    o.w = (v.w - mu) * rstd * gg.w + bb.w;
    *(float4*)(y + (long long)row * DD + t * 4) = o;
}

// ---------------------------------------------------------------------------
extern "C" void kernel_launch(void* const* d_in, const int* in_sizes, int n_in,
                              void* d_out, int out_size)
{
    const float* emb      = (const float*)d_in[0];
    const float* pos      = (const float*)d_in[1];
    const float* c_attn_w = (const float*)d_in[2];
    const float* c_attn_b = (const float*)d_in[3];
    const float* out_w    = (const float*)d_in[4];
    const float* out_b    = (const float*)d_in[5];
    const float* ln1_g    = (const float*)d_in[6];
    const float* ln1_b    = (const float*)d_in[7];
    const float* c_fc_w   = (const float*)d_in[8];
    const float* c_fc_b   = (const float*)d_in[9];
    const float* c_proj_w = (const float*)d_in[10];
    const float* c_proj_b = (const float*)d_in[11];
    const float* ln2_g    = (const float*)d_in[12];
    const float* ln2_b    = (const float*)d_in[13];
    (void)in_sizes; (void)n_in; (void)out_size;

    float *h_, *x_, *qkv_, *ao_, *fc_, *wt_, *vt_;
    cudaGetSymbolAddress((void**)&h_,   g_h);
    cudaGetSymbolAddress((void**)&x_,   g_x);
    cudaGetSymbolAddress((void**)&qkv_, g_qkv);
    cudaGetSymbolAddress((void**)&ao_,  g_ao);
    cudaGetSymbolAddress((void**)&fc_,  g_fc);
    cudaGetSymbolAddress((void**)&wt_,  g_wt);
    cudaGetSymbolAddress((void**)&vt_,  g_vt);

    const int SM128 = 3 * (128 + 128) * 128;   // 98304
    const int SMFL  = 98304;
    cudaFuncSetAttribute(mgemm<128>, cudaFuncAttributeMaxDynamicSharedMemorySize, SM128);
    cudaFuncSetAttribute(flash_attn, cudaFuncAttributeMaxDynamicSharedMemorySize, SMFL);

    dim3 tb(32, 8);

    addpos_k<<<(TOK * DD) / 256, 256>>>(emb, pos, h_);

    for (int l = 0; l < LL; l++) {
        const float* aw = c_attn_w + (long long)l * DD * 3 * DD;
        const float* ab = c_attn_b + (long long)l * 3 * DD;
        const float* ow = out_w    + (long long)l * DD * DD;
        const float* ob = out_b    + (long long)l * DD;
        const float* fw = c_fc_w   + (long long)l * DD * 4 * DD;
        const float* fb = c_fc_b   + (long long)l * 4 * DD;
        const float* pw = c_proj_w + (long long)l * 4 * DD * DD;
        const float* pb = c_proj_b + (long long)l * DD;

        // Weight transposes -> K-major B operands
        transpose_k<<<dim3(3*DD/32, DD/32, 1), tb>>>(aw, wt_ + AW_T, 3*DD, DD, 0,0,0,0);
        transpose_k<<<dim3(DD/32,   DD/32, 1), tb>>>(ow, wt_ + OW_T, DD,   DD, 0,0,0,0);
        transpose_k<<<dim3(4*DD/32, DD/32, 1), tb>>>(fw, wt_ + FW_T, 4*DD, DD, 0,0,0,0);
        transpose_k<<<dim3(DD/32, 4*DD/32, 1), tb>>>(pw, wt_ + PW_T, DD, 4*DD, 0,0,0,0);

        // x = LN1(h)
        layernorm_k<<<TOK, 128>>>(h_, ln1_g + l * DD, ln1_b + l * DD, x_);

        // qkv = x @ c_attn_w + b     [4096,1536] K=512
        mgemm<128><<<dim3(3*DD/128, TOK/128, 1), 256, SM128>>>(
            x_, wt_ + AW_T, ab, nullptr, qkv_,
            DD, DD, DD, 3*DD, 0,0,0,0,0,0, 1.0f, 0);

        // vt[b*h][hd][n] = V^T
        transpose_k<<<dim3(HDIM/32, NN/32, BB*HH), tb>>>(
            qkv_ + 2*DD, vt_, 3*DD, NN,
            (long long)NN*3*DD, HDIM,
            (long long)HH*HDIM*NN, (long long)HDIM*NN);

        // fused attention -> ao (heads merged)
        flash_attn<<<dim3(NN/128, 1, BB*HH), 256, SMFL>>>(qkv_, vt_, ao_);

        // h = ao @ out_w + out_b + h   [4096,512] K=512
        mgemm<128><<<dim3(DD/128, TOK/128, 1), 256, SM128>>>(
            ao_, wt_ + OW_T, ob, h_, h_,
            DD, DD, DD, DD, 0,0,0,0,0,0, 1.0f, 0);

        // x = LN2(h)
        layernorm_k<<<TOK, 128>>>(h_, ln2_g + l * DD, ln2_b + l * DD, x_);

        // fc = gelu(x @ c_fc_w + b)  [4096,2048] K=512
        mgemm<128><<<dim3(4*DD/128, TOK/128, 1), 256, SM128>>>(
            x_, wt_ + FW_T, fb, nullptr, fc_,
            DD, DD, DD, 4*DD, 0,0,0,0,0,0, 1.0f, 1);

        // h = fc @ c_proj_w + b + h  [4096,512] K=2048
        float* dst = (l == LL - 1) ? (float*)d_out : h_;
        mgemm<128><<<dim3(DD/128, TOK/128, 1), 256, SM128>>>(
            fc_, wt_ + PW_T, pb, h_, dst,
            4*DD, 4*DD, 4*DD, DD, 0,0,0,0,0,0, 1.0f, 0);
    }
}

// round 6
// speedup vs baseline: 7.1057x; 1.6849x over previous
#include <cuda_runtime.h>
#include <cuda_fp16.h>
#include <cstdint>
#include <math.h>

// Problem constants
#define BB 2
#define NN 2048
#define DD 512
#define HH 8
#define HDIM 64
#define LL 2
#define TOK (BB*NN)          // 4096 rows

// Scratch (device globals — no allocation allowed)
__device__ float  g_h   [(size_t)TOK * DD];           // residual stream (fp32)
__device__ __half g_xh  [(size_t)TOK * DD];           // LN output
__device__ __half g_qkvh[(size_t)TOK * 3 * DD];       // qkv
__device__ __half g_aoh [(size_t)TOK * DD];           // attention out
__device__ __half g_fch [(size_t)TOK * 4 * DD];       // MLP hidden
__device__ __half g_wth [3145728];                    // transposed weights (one layer)
__device__ __half g_vth [(size_t)BB * HH * HDIM * NN];// V^T [b*h][hd][n]

#define AW_T 0          // [1536,512]
#define OW_T 786432     // [512,512]
#define FW_T 1048576    // [2048,512]
#define PW_T 2097152    // [512,2048]

// ---------------------------------------------------------------------------
__device__ __forceinline__ uint32_t smem_u32(const void* p) {
    uint32_t a;
    asm("{ .reg .u64 t; cvta.to.shared.u64 t, %1; cvt.u32.u64 %0, t; }" : "=r"(a) : "l"(p));
    return a;
}
__device__ __forceinline__ void cpa16(uint32_t saddr, const void* g) {
    asm volatile("cp.async.cg.shared.global [%0], [%1], 16;" :: "r"(saddr), "l"(g));
}
#define CP_COMMIT() asm volatile("cp.async.commit_group;" ::: "memory")
#define CP_WAIT(n)  asm volatile("cp.async.wait_group %0;" :: "n"(n) : "memory")
__device__ __forceinline__ void ldsm4(uint32_t& r0, uint32_t& r1, uint32_t& r2, uint32_t& r3,
                                      uint32_t addr) {
    asm volatile("ldmatrix.sync.aligned.m8n8.x4.shared.b16 {%0,%1,%2,%3}, [%4];"
                 : "=r"(r0), "=r"(r1), "=r"(r2), "=r"(r3) : "r"(addr));
}
// m16n8k16 fp16 mma, fp32 accumulate
__device__ __forceinline__ void mma16(float* d, const uint32_t* a, const uint32_t* b) {
    asm volatile(
        "mma.sync.aligned.m16n8k16.row.col.f32.f16.f16.f32 "
        "{%0,%1,%2,%3}, {%4,%5,%6,%7}, {%8,%9}, {%0,%1,%2,%3};"
        : "+f"(d[0]), "+f"(d[1]), "+f"(d[2]), "+f"(d[3])
        : "r"(a[0]), "r"(a[1]), "r"(a[2]), "r"(a[3]), "r"(b[0]), "r"(b[1]));
}
__device__ __forceinline__ float gelu_new(float x) {
    float x3 = x * x * x;
    return 0.5f * x * (1.0f + tanhf(0.7978845608028654f * (x + 0.044715f * x3)));
}

// ---------------------------------------------------------------------------
// fp16 tensor-core GEMM, cp.async 3-stage pipeline.
// C[M,N] = (A @ B^T) + bias (+GELU) (+res).  Out fp32 or fp16.
// A: [M,K] half K-major (lda). B: [N,K] half K-major (ldb). CTA tile 128x128.
// BK = 64 halfs = 128B swizzled row. 256 threads = 8 warps (2m x 4n).
// ---------------------------------------------------------------------------
__global__ void __launch_bounds__(256, 2)
hgemm(const __half* __restrict__ A, const __half* __restrict__ B,
      const float* __restrict__ bias, const float* res, void* Cv,
      int K, int lda, int ldb, int ldc, int act, int outHalf)
{
    constexpr int ABYT = 128 * 128;          // 16KB
    constexpr int STAGE = 2 * ABYT;          // A + B
    constexpr int NS = 3;

    extern __shared__ char smem[];
    uint32_t sbase = smem_u32(smem);

    const int t = threadIdx.x;
    const int lane = t & 31;
    const int w = t >> 5, wm = w >> 2, wn = w & 3;
    const int m0 = blockIdx.y * 128;
    const int n0 = blockIdx.x * 128;

    float acc[4][4][4];
    #pragma unroll
    for (int i = 0; i < 4; i++)
        #pragma unroll
        for (int j = 0; j < 4; j++)
            #pragma unroll
            for (int q = 0; q < 4; q++) acc[i][j][q] = 0.f;

    const int KT = K / 64;
    const int lc8 = t & 7;          // 16B chunk within row

    auto issue = [&](int kt) {
        int st = kt % NS;
        uint32_t sA = sbase + st * STAGE;
        const __half* Ak = A + kt * 64 + lc8 * 8;
        #pragma unroll
        for (int i = 0; i < 4; i++) {
            int r = (t + i * 256) >> 3;
            cpa16(sA + r * 128 + ((lc8 ^ (r & 7)) << 4),
                  Ak + (long long)(m0 + r) * lda);
        }
        uint32_t sB = sA + ABYT;
        const __half* Bk = B + kt * 64 + lc8 * 8;
        #pragma unroll
        for (int i = 0; i < 4; i++) {
            int r = (t + i * 256) >> 3;
            cpa16(sB + r * 128 + ((lc8 ^ (r & 7)) << 4),
                  Bk + (long long)(n0 + r) * ldb);
        }
    };

    #pragma unroll
    for (int s = 0; s < NS - 1; s++) {
        if (s < KT) issue(s);
        CP_COMMIT();
    }

    const int arow0 = wm * 64 + (lane & 7) + ((lane >> 3) & 1) * 8;
    const int ach0  = lane >> 4;
    const int brow0 = wn * 32 + ((lane >> 4) & 1) * 8 + (lane & 7);
    const int bch0  = (lane >> 3) & 1;

    for (int kt = 0; kt < KT; kt++) {
        if (kt + NS - 1 < KT) issue(kt + NS - 1);
        CP_COMMIT();
        CP_WAIT(NS - 1);
        __syncthreads();

        uint32_t sA = sbase + (kt % NS) * STAGE;
        uint32_t sB = sA + ABYT;
        #pragma unroll
        for (int kb = 0; kb < 4; kb++) {      // 4 x k16 per 64-K stage
            uint32_t a[4][4];
            #pragma unroll
            for (int mi = 0; mi < 4; mi++) {
                int r = arow0 + mi * 16;
                uint32_t ad = sA + r * 128 + (((kb * 2 + ach0) ^ (r & 7)) << 4);
                ldsm4(a[mi][0], a[mi][1], a[mi][2], a[mi][3], ad);
            }
            uint32_t b[2][4];
            #pragma unroll
            for (int g = 0; g < 2; g++) {
                int r = brow0 + g * 16;
                uint32_t bd = sB + r * 128 + (((kb * 2 + bch0) ^ (r & 7)) << 4);
                ldsm4(b[g][0], b[g][1], b[g][2], b[g][3], bd);
            }
            #pragma unroll
            for (int mi = 0; mi < 4; mi++)
                #pragma unroll
                for (int ni = 0; ni < 4; ni++)
                    mma16(acc[mi][ni], a[mi], &b[ni >> 1][(ni & 1) * 2]);
        }
        __syncthreads();
    }

    const int gid = lane >> 2, cq = lane & 3;
    float* Cf = (float*)Cv;
    __half* Ch = (__half*)Cv;
    #pragma unroll
    for (int mi = 0; mi < 4; mi++) {
        #pragma unroll
        for (int ni = 0; ni < 4; ni++) {
            int r = m0 + wm * 64 + mi * 16 + gid;
            int c = n0 + wn * 32 + ni * 8 + cq * 2;
            float2 bv = bias ? *(const float2*)(bias + c) : make_float2(0.f, 0.f);
            #pragma unroll
            for (int half_ = 0; half_ < 2; half_++) {
                int row = r + half_ * 8;
                float v0 = acc[mi][ni][half_ * 2 + 0] + bv.x;
                float v1 = acc[mi][ni][half_ * 2 + 1] + bv.y;
                if (act) { v0 = gelu_new(v0); v1 = gelu_new(v1); }
                if (res) {
                    float2 rv = *(const float2*)(res + (long long)row * ldc + c);
                    v0 += rv.x; v1 += rv.y;
                }
                if (outHalf) {
                    *(__half2*)(Ch + (long long)row * ldc + c) = __floats2half2_rn(v0, v1);
                } else {
                    float2 o; o.x = v0; o.y = v1;
                    *(float2*)(Cf + (long long)row * ldc + c) = o;
                }
            }
        }
    }
}

// ---------------------------------------------------------------------------
// Fused flash attention (fp16 mma, fp32 online softmax, exclude-self mask).
// Grid (NN/128, 1, BB*HH), 256 threads (8 warps x 16 q-rows).
// SMEM (48KB): sQ/sP alias [0,16K); stage st: K at 16K+st*16K, V at +8K.
// ---------------------------------------------------------------------------
#define FCHUNK 64
__global__ void __launch_bounds__(256, 2)
flash_attn(const __half* __restrict__ qkv, const __half* __restrict__ vt,
           __half* __restrict__ ao)
{
    extern __shared__ char smem[];
    uint32_t sb = smem_u32(smem);
    const int t = threadIdx.x;
    const int lane = t & 31;
    const int w = t >> 5;
    const int q0 = blockIdx.x * 128;
    const int z = blockIdx.z;
    const int zb = z / HH, zh = z % HH;

    const __half* Qg = qkv + (long long)zb * NN * 3 * DD + zh * HDIM;
    const __half* Kg = Qg + DD;
    const __half* Vt = vt + (long long)z * HDIM * NN;

    auto issue_kv = [&](int ch) {
        int st = ch & 1;
        int c0 = ch * FCHUNK;
        uint32_t sK = sb + 16384 + st * 16384;
        uint32_t sV = sK + 8192;
        #pragma unroll
        for (int i = 0; i < 2; i++) {
            int idx = t + i * 256;
            int r = idx >> 3, c8 = idx & 7;
            uint32_t so = r * 128 + ((c8 ^ (r & 7)) << 4);
            cpa16(sK + so, Kg + (long long)(c0 + r) * (3 * DD) + c8 * 8);
            cpa16(sV + so, Vt + (long long)r * NN + c0 + c8 * 8);
        }
    };

    // Q -> sQ (group 1), KV chunk 0 (group 2)
    #pragma unroll
    for (int i = 0; i < 4; i++) {
        int idx = t + i * 256;
        int r = idx >> 3, c8 = idx & 7;
        cpa16(sb + r * 128 + ((c8 ^ (r & 7)) << 4),
              Qg + (long long)(q0 + r) * (3 * DD) + c8 * 8);
    }
    CP_COMMIT();
    issue_kv(0);
    CP_COMMIT();
    CP_WAIT(1);          // Q resident
    __syncthreads();

    // Persistent Q fragments (m16 x k64 per warp): 4 k16 blocks
    const int arow = w * 16 + (lane & 7) + ((lane >> 3) & 1) * 8;
    const int qsel = lane >> 4;
    uint32_t aQ[4][4];
    #pragma unroll
    for (int kb = 0; kb < 4; kb++) {
        uint32_t ad = sb + arow * 128 + (((kb * 2 + qsel) ^ (arow & 7)) << 4);
        ldsm4(aQ[kb][0], aQ[kb][1], aQ[kb][2], aQ[kb][3], ad);
    }
    __syncthreads();     // Q frags in regs before sP overwrites region

    const int brow = ((lane >> 4) & 1) * 8 + (lane & 7);
    const int bsel = (lane >> 3) & 1;
    const int gid = lane >> 2, cq = lane & 3;
    const int row0 = q0 + w * 16 + gid;

    float m0 = -1e30f, m1 = -1e30f, l0 = 0.f, l1 = 0.f;
    float accO[8][4];
    #pragma unroll
    for (int j = 0; j < 8; j++)
        #pragma unroll
        for (int q = 0; q < 4; q++) accO[j][q] = 0.f;

    const int NCH = NN / FCHUNK;   // 32
    for (int ch = 0; ch < NCH; ch++) {
        if (ch + 1 < NCH) issue_kv(ch + 1);
        CP_COMMIT();
        CP_WAIT(1);
        __syncthreads();

        int st = ch & 1;
        uint32_t sK = sb + 16384 + st * 16384;
        uint32_t sV = sK + 8192;

        // ---- S = Q @ K^T; 0.125 scale post-mma (exact)
        float accS[8][4];
        #pragma unroll
        for (int j = 0; j < 8; j++)
            #pragma unroll
            for (int q = 0; q < 4; q++) accS[j][q] = 0.f;

        #pragma unroll
        for (int kb = 0; kb < 4; kb++) {
            uint32_t b[4][4];
            #pragma unroll
            for (int g = 0; g < 4; g++) {
                int r = g * 16 + brow;
                uint32_t bd = sK + r * 128 + (((kb * 2 + bsel) ^ (r & 7)) << 4);
                ldsm4(b[g][0], b[g][1], b[g][2], b[g][3], bd);
            }
            #pragma unroll
            for (int j = 0; j < 8; j++)
                mma16(accS[j], aQ[kb], &b[j >> 1][(j & 1) * 2]);
        }

        // ---- scale + exclude-self mask
        int c0 = ch * FCHUNK;
        #pragma unroll
        for (int j = 0; j < 8; j++) {
            accS[j][0] *= 0.125f; accS[j][1] *= 0.125f;
            accS[j][2] *= 0.125f; accS[j][3] *= 0.125f;
            int col = c0 + j * 8 + cq * 2;
            if (col     == row0    ) accS[j][0] = -1e30f;
            if (col + 1 == row0    ) accS[j][1] = -1e30f;
            if (col     == row0 + 8) accS[j][2] = -1e30f;
            if (col + 1 == row0 + 8) accS[j][3] = -1e30f;
        }

        // ---- online softmax (fp32)
        float cm0 = -1e30f, cm1 = -1e30f;
        #pragma unroll
        for (int j = 0; j < 8; j++) {
            cm0 = fmaxf(cm0, fmaxf(accS[j][0], accS[j][1]));
            cm1 = fmaxf(cm1, fmaxf(accS[j][2], accS[j][3]));
        }
        cm0 = fmaxf(cm0, __shfl_xor_sync(0xffffffffu, cm0, 1));
        cm0 = fmaxf(cm0, __shfl_xor_sync(0xffffffffu, cm0, 2));
        cm1 = fmaxf(cm1, __shfl_xor_sync(0xffffffffu, cm1, 1));
        cm1 = fmaxf(cm1, __shfl_xor_sync(0xffffffffu, cm1, 2));
        float nm0 = fmaxf(m0, cm0), nm1 = fmaxf(m1, cm1);
        float sc0 = __expf(m0 - nm0), sc1 = __expf(m1 - nm1);
        m0 = nm0; m1 = nm1;

        float ps0 = 0.f, ps1 = 0.f;
        #pragma unroll
        for (int j = 0; j < 8; j++) {
            accS[j][0] = __expf(accS[j][0] - nm0);
            accS[j][1] = __expf(accS[j][1] - nm0);
            accS[j][2] = __expf(accS[j][2] - nm1);
            accS[j][3] = __expf(accS[j][3] - nm1);
            ps0 += accS[j][0] + accS[j][1];
            ps1 += accS[j][2] + accS[j][3];
        }
        ps0 += __shfl_xor_sync(0xffffffffu, ps0, 1);
        ps0 += __shfl_xor_sync(0xffffffffu, ps0, 2);
        ps1 += __shfl_xor_sync(0xffffffffu, ps1, 1);
        ps1 += __shfl_xor_sync(0xffffffffu, ps1, 2);
        l0 = l0 * sc0 + ps0;
        l1 = l1 * sc1 + ps1;

        #pragma unroll
        for (int j = 0; j < 8; j++) {
            accO[j][0] *= sc0; accO[j][1] *= sc0;
            accO[j][2] *= sc1; accO[j][3] *= sc1;
        }

        // ---- P (fp16) -> sP (aliases sQ; rows warp-private)
        int pr0 = w * 16 + gid, pr1 = pr0 + 8;
        #pragma unroll
        for (int j = 0; j < 8; j++) {
            *(__half2*)(smem + pr0 * 128 + ((j ^ (pr0 & 7)) << 4) + cq * 4) =
                __floats2half2_rn(accS[j][0], accS[j][1]);
            *(__half2*)(smem + pr1 * 128 + ((j ^ (pr1 & 7)) << 4) + cq * 4) =
                __floats2half2_rn(accS[j][2], accS[j][3]);
        }
        __syncwarp();

        // ---- O += P @ V
        #pragma unroll
        for (int kb = 0; kb < 4; kb++) {
            uint32_t aP[4];
            uint32_t ad = sb + arow * 128 + (((kb * 2 + qsel) ^ (arow & 7)) << 4);
            ldsm4(aP[0], aP[1], aP[2], aP[3], ad);
            uint32_t bv[4][4];
            #pragma unroll
            for (int g = 0; g < 4; g++) {
                int r = g * 16 + brow;
                uint32_t bd = sV + r * 128 + (((kb * 2 + bsel) ^ (r & 7)) << 4);
                ldsm4(bv[g][0], bv[g][1], bv[g][2], bv[g][3], bd);
            }
            #pragma unroll
            for (int j = 0; j < 8; j++)
                mma16(accO[j], aP, &bv[j >> 1][(j & 1) * 2]);
        }
        __syncthreads();
    }

    // ---- write O (fp16)
    float inv0 = 1.0f / l0, inv1 = 1.0f / l1;
    __half* ao0 = ao + ((long long)zb * NN + row0) * DD + zh * HDIM;
    __half* ao1 = ao0 + 8 * DD;
    #pragma unroll
    for (int j = 0; j < 8; j++) {
        int c = j * 8 + cq * 2;
        *(__half2*)(ao0 + c) = __floats2half2_rn(accO[j][0] * inv0, accO[j][1] * inv0);
        *(__half2*)(ao1 + c) = __floats2half2_rn(accO[j][2] * inv1, accO[j][3] * inv1);
    }
}

// ---------------------------------------------------------------------------
// Tiled transpose with dtype convert: dst[C,R] = (TO)src[R,C]^T, batched.
// ---------------------------------------------------------------------------
template<typename TI, typename TO>
__global__ void transpose_t(const TI* __restrict__ src, TO* __restrict__ dst,
                            int lds, int ldd,
                            long long szb, long long szh, long long dzb, long long dzh)
{
    __shared__ float tile[32][33];
    int z = blockIdx.z, zb = z / HH, zh = z % HH;
    src += (long long)zb * szb + (long long)zh * szh;
    dst += (long long)zb * dzb + (long long)zh * dzh;
    int c0 = blockIdx.x * 32, r0 = blockIdx.y * 32;
    int tx = threadIdx.x, ty = threadIdx.y;   // 32 x 8
    #pragma unroll
    for (int i = 0; i < 32; i += 8)
        tile[ty + i][tx] = (float)src[(long long)(r0 + ty + i) * lds + c0 + tx];
    __syncthreads();
    #pragma unroll
    for (int i = 0; i < 32; i += 8)
        dst[(long long)(c0 + ty + i) * ldd + r0 + tx] = (TO)tile[tx][ty + i];
}

__global__ void addpos_k(const float* __restrict__ e, const float* __restrict__ p,
                         float* __restrict__ h)
{
    long long i = (long long)blockIdx.x * 256 + threadIdx.x;
    long long nd = i % ((long long)NN * DD);
    h[i] = e[i] + p[nd];
}

// LayerNorm: fp32 in (residual stream), fp16 out (GEMM operand)
__global__ void layernorm_h(const float* __restrict__ x, const float* __restrict__ g,
                            const float* __restrict__ b, __half* __restrict__ y)
{
    int row = blockIdx.x;
    int t = threadIdx.x;
    const float* xr = x + (long long)row * DD;
    float4 v = *(const float4*)(xr + t * 4);
    float s  = v.x + v.y + v.z + v.w;
    float ss = v.x*v.x + v.y*v.y + v.z*v.z + v.w*v.w;
    #pragma unroll
    for (int o = 16; o; o >>= 1) {
        s  += __shfl_xor_sync(0xffffffffu, s,  o);
        ss += __shfl_xor_sync(0xffffffffu, ss, o);
    }
    __shared__ float r1[4], r2[4];
    int wid = t >> 5, lane = t & 31;
    if (lane == 0) { r1[wid] = s; r2[wid] = ss; }
    __syncthreads();
    float sum   = r1[0] + r1[1] + r1[2] + r1[3];
    float sumsq = r2[0] + r2[1] + r2[2] + r2[3];
    float mu   = sum * (1.0f / DD);
    float var  = sumsq * (1.0f / DD) - mu * mu;
    float rstd = rsqrtf(var + 1e-5f);
    float4 gg = *(const float4*)(g + t * 4);
    float4 bb = *(const float4*)(b + t * 4);
    float o0 = (v.x - mu) * rstd * gg.x + bb.x;
    float o1 = (v.y - mu) * rstd * gg.y + bb.y;
    float o2 = (v.z - mu) * rstd * gg.z + bb.z;
    float o3 = (v.w - mu) * rstd * gg.w + bb.w;
    __half2* yp = (__half2*)(y + (long long)row * DD + t * 4);
    yp[0] = __floats2half2_rn(o0, o1);
    yp[1] = __floats2half2_rn(o2, o3);
}

// ---------------------------------------------------------------------------
extern "C" void kernel_launch(void* const* d_in, const int* in_sizes, int n_in,
                              void* d_out, int out_size)
{
    const float* emb      = (const float*)d_in[0];
    const float* pos      = (const float*)d_in[1];
    const float* c_attn_w = (const float*)d_in[2];
    const float* c_attn_b = (const float*)d_in[3];
    const float* out_w    = (const float*)d_in[4];
    const float* out_b    = (const float*)d_in[5];
    const float* ln1_g    = (const float*)d_in[6];
    const float* ln1_b    = (const float*)d_in[7];
    const float* c_fc_w   = (const float*)d_in[8];
    const float* c_fc_b   = (const float*)d_in[9];
    const float* c_proj_w = (const float*)d_in[10];
    const float* c_proj_b = (const float*)d_in[11];
    const float* ln2_g    = (const float*)d_in[12];
    const float* ln2_b    = (const float*)d_in[13];
    (void)in_sizes; (void)n_in; (void)out_size;

    float  *h_;
    __half *xh_, *qkvh_, *aoh_, *fch_, *wth_, *vth_;
    cudaGetSymbolAddress((void**)&h_,    g_h);
    cudaGetSymbolAddress((void**)&xh_,   g_xh);
    cudaGetSymbolAddress((void**)&qkvh_, g_qkvh);
    cudaGetSymbolAddress((void**)&aoh_,  g_aoh);
    cudaGetSymbolAddress((void**)&fch_,  g_fch);
    cudaGetSymbolAddress((void**)&wth_,  g_wth);
    cudaGetSymbolAddress((void**)&vth_,  g_vth);

    const int SMG  = 3 * 32768;    // 98304
    const int SMFL = 49152;
    cudaFuncSetAttribute(hgemm, cudaFuncAttributeMaxDynamicSharedMemorySize, SMG);
    cudaFuncSetAttribute(flash_attn, cudaFuncAttributeMaxDynamicSharedMemorySize, SMFL);

    dim3 tb(32, 8);

    addpos_k<<<(TOK * DD) / 256, 256>>>(emb, pos, h_);

    for (int l = 0; l < LL; l++) {
        const float* aw = c_attn_w + (long long)l * DD * 3 * DD;
        const float* ab = c_attn_b + (long long)l * 3 * DD;
        const float* ow = out_w    + (long long)l * DD * DD;
        const float* ob = out_b    + (long long)l * DD;
        const float* fw = c_fc_w   + (long long)l * DD * 4 * DD;
        const float* fb = c_fc_b   + (long long)l * 4 * DD;
        const float* pw = c_proj_w + (long long)l * 4 * DD * DD;
        const float* pb = c_proj_b + (long long)l * DD;

        // Weight transposes -> K-major fp16 B operands
        transpose_t<float,__half><<<dim3(3*DD/32, DD/32, 1), tb>>>(aw, wth_ + AW_T, 3*DD, DD, 0,0,0,0);
        transpose_t<float,__half><<<dim3(DD/32,   DD/32, 1), tb>>>(ow, wth_ + OW_T, DD,   DD, 0,0,0,0);
        transpose_t<float,__half><<<dim3(4*DD/32, DD/32, 1), tb>>>(fw, wth_ + FW_T, 4*DD, DD, 0,0,0,0);
        transpose_t<float,__half><<<dim3(DD/32, 4*DD/32, 1), tb>>>(pw, wth_ + PW_T, DD, 4*DD, 0,0,0,0);

        // x = LN1(h) -> fp16
        layernorm_h<<<TOK, 128>>>(h_, ln1_g + l * DD, ln1_b + l * DD, xh_);

        // qkv = x @ c_attn_w + b   [4096,1536] K=512, out fp16
        hgemm<<<dim3(3*DD/128, TOK/128, 1), 256, SMG>>>(
            xh_, wth_ + AW_T, ab, nullptr, qkvh_,
            DD, DD, DD, 3*DD, 0, 1);

        // vt[b*h][hd][n] = V^T (fp16 -> fp16)
        transpose_t<__half,__half><<<dim3(HDIM/32, NN/32, BB*HH), tb>>>(
            qkvh_ + 2*DD, vth_, 3*DD, NN,
            (long long)NN*3*DD, HDIM,
            (long long)HH*HDIM*NN, (long long)HDIM*NN);

        // fused attention -> ao (fp16, heads merged)
        flash_attn<<<dim3(NN/128, 1, BB*HH), 256, SMFL>>>(qkvh_, vth_, aoh_);

        // h = ao @ out_w + out_b + h   [4096,512] K=512, out fp32
        hgemm<<<dim3(DD/128, TOK/128, 1), 256, SMG>>>(
            aoh_, wth_ + OW_T, ob, h_, h_,
            DD, DD, DD, DD, 0, 0);

        // x = LN2(h) -> fp16
        layernorm_h<<<TOK, 128>>>(h_, ln2_g + l * DD, ln2_b + l * DD, xh_);

        // fc = gelu(x @ c_fc_w + b)  [4096,2048] K=512, out fp16
        hgemm<<<dim3(4*DD/128, TOK/128, 1), 256, SMG>>>(
            xh_, wth_ + FW_T, fb, nullptr, fch_,
            DD, DD, DD, 4*DD, 1, 1);

        // h = fc @ c_proj_w + b + h  [4096,512] K=2048, out fp32
        float* dst = (l == LL - 1) ? (float*)d_out : h_;
        hgemm<<<dim3(DD/128, TOK/128, 1), 256, SMG>>>(
            fch_, wth_ + PW_T, pb, h_, dst,
            4*DD, 4*DD, 4*DD, DD, 0, 0);
    }
}